// round 1
// baseline (speedup 1.0000x reference)
#include <cuda_runtime.h>

// L2O GRU step: per-row gradient preprocess -> GRUCell(HID=8) -> Dense(1) -> -exp(.)*g
// Layout of d_out (9N floats): [0, 8N) = h_new row-major, [8N, 9N) = out.

#define HID 8

__device__ __forceinline__ float sigf(float x) {
    // 1/(1+exp(-x)) : MUFU ex2 + MUFU rcp
    float e = __expf(-x);
    return __fdividef(1.0f, 1.0f + e);
}

__device__ __forceinline__ float tanh_fast(float x) {
    // tanh via exp, overflow-safe: MUFU ex2 + MUFU rcp
    float ax = fabsf(x);
    float e  = __expf(-2.0f * ax);
    float y  = __fdividef(1.0f - e, 1.0f + e);
    return copysignf(y, x);
}

__global__ void __launch_bounds__(256)
l2o_gru_kernel(const float* __restrict__ h,    const float* __restrict__ g,
               const float* __restrict__ Wi_r, const float* __restrict__ Wh_r, const float* __restrict__ bh_r,
               const float* __restrict__ Wi_z, const float* __restrict__ Wh_z, const float* __restrict__ bh_z,
               const float* __restrict__ Wi_n, const float* __restrict__ Wh_n, const float* __restrict__ bh_n,
               const float* __restrict__ Wm,   const float* __restrict__ bm,
               float* __restrict__ out_h, float* __restrict__ out_o, int N)
{
    // Shared weights: indices 0=r, 1=z, 2=n
    __shared__ float sWh[3][64];
    __shared__ float sWi[3][16];
    __shared__ float sbh[3][8];
    __shared__ float sWm[8];
    __shared__ float sbm;

    const int t = threadIdx.x;
    if (t < 64) { sWh[0][t] = Wh_r[t]; sWh[1][t] = Wh_z[t]; sWh[2][t] = Wh_n[t]; }
    if (t < 16) { sWi[0][t] = Wi_r[t]; sWi[1][t] = Wi_z[t]; sWi[2][t] = Wi_n[t]; }
    if (t < 8)  { sbh[0][t] = bh_r[t]; sbh[1][t] = bh_z[t]; sbh[2][t] = bh_n[t]; sWm[t] = Wm[t]; }
    if (t == 0) { sbm = bm[0]; }
    __syncthreads();

    const int base = blockIdx.x * 512;
    int rows[2];
    rows[0] = base + t;
    rows[1] = base + 256 + t;

    float hv[2][HID];
    float gin0[2], gin1[2], gval[2];

    #pragma unroll
    for (int p = 0; p < 2; p++) {
        int row = rows[p] < N ? rows[p] : (N - 1);   // clamp; stores are guarded
        const float4* hp = reinterpret_cast<const float4*>(h + (size_t)row * HID);
        float4 a = __ldg(hp);
        float4 b = __ldg(hp + 1);
        hv[p][0] = a.x; hv[p][1] = a.y; hv[p][2] = a.z; hv[p][3] = a.w;
        hv[p][4] = b.x; hv[p][5] = b.y; hv[p][6] = b.z; hv[p][7] = b.w;

        float gv = __ldg(g + row);
        gval[p] = gv;
        float glog = __logf(fabsf(gv) + 1e-8f) * 0.1f;           // log(|g|+eps)/P
        float gs   = (gv > 0.0f) ? 1.0f : ((gv < 0.0f) ? -1.0f : 0.0f);
        if (glog >= -1.0f) { gin0[p] = glog;  gin1[p] = gs; }
        else               { gin0[p] = -1.0f; gin1[p] = 22026.4658203125f * gv; } // exp(10)*g
    }

    float zz[2][HID], rr[2][HID];

    // z gate
    #pragma unroll
    for (int j = 0; j < HID; j++) {
        float b  = sbh[1][j];
        float w0 = sWi[1][j], w1 = sWi[1][HID + j];
        float a0 = fmaf(gin1[0], w1, fmaf(gin0[0], w0, b));
        float a1 = fmaf(gin1[1], w1, fmaf(gin0[1], w0, b));
        #pragma unroll
        for (int k = 0; k < HID; k++) {
            float w = sWh[1][k * HID + j];
            a0 = fmaf(hv[0][k], w, a0);
            a1 = fmaf(hv[1][k], w, a1);
        }
        zz[0][j] = sigf(a0);
        zz[1][j] = sigf(a1);
    }

    // r gate
    #pragma unroll
    for (int j = 0; j < HID; j++) {
        float b  = sbh[0][j];
        float w0 = sWi[0][j], w1 = sWi[0][HID + j];
        float a0 = fmaf(gin1[0], w1, fmaf(gin0[0], w0, b));
        float a1 = fmaf(gin1[1], w1, fmaf(gin0[1], w0, b));
        #pragma unroll
        for (int k = 0; k < HID; k++) {
            float w = sWh[0][k * HID + j];
            a0 = fmaf(hv[0][k], w, a0);
            a1 = fmaf(hv[1][k], w, a1);
        }
        rr[0][j] = sigf(a0);
        rr[1][j] = sigf(a1);
    }

    // candidate n, h_new, and MLP output accumulation
    float sb = sbm;
    float outs[2] = { sb, sb };
    float hn[2][HID];

    #pragma unroll
    for (int j = 0; j < HID; j++) {
        float b  = sbh[2][j];
        float a0 = b, a1 = b;
        #pragma unroll
        for (int k = 0; k < HID; k++) {
            float w = sWh[2][k * HID + j];
            a0 = fmaf(hv[0][k], w, a0);
            a1 = fmaf(hv[1][k], w, a1);
        }
        float w0 = sWi[2][j], w1 = sWi[2][HID + j];
        float p0 = fmaf(rr[0][j], a0, fmaf(gin1[0], w1, gin0[0] * w0));
        float p1 = fmaf(rr[1][j], a1, fmaf(gin1[1], w1, gin0[1] * w0));
        float n0 = tanh_fast(p0);
        float n1 = tanh_fast(p1);
        float h0 = fmaf(zz[0][j], hv[0][j], (1.0f - zz[0][j]) * n0);
        float h1 = fmaf(zz[1][j], hv[1][j], (1.0f - zz[1][j]) * n1);
        hn[0][j] = h0;
        hn[1][j] = h1;
        float wm = sWm[j];
        outs[0] = fmaf(h0, wm, outs[0]);
        outs[1] = fmaf(h1, wm, outs[1]);
    }

    #pragma unroll
    for (int p = 0; p < 2; p++) {
        int row = rows[p];
        if (row < N) {
            float4* op = reinterpret_cast<float4*>(out_h + (size_t)row * HID);
            float4 a, b;
            a.x = hn[p][0]; a.y = hn[p][1]; a.z = hn[p][2]; a.w = hn[p][3];
            b.x = hn[p][4]; b.y = hn[p][5]; b.z = hn[p][6]; b.w = hn[p][7];
            op[0] = a;
            op[1] = b;
            out_o[row] = -__expf(outs[p]) * gval[p];
        }
    }
}

extern "C" void kernel_launch(void* const* d_in, const int* in_sizes, int n_in,
                              void* d_out, int out_size) {
    const float* h    = (const float*)d_in[0];
    const float* g    = (const float*)d_in[1];
    const float* Wi_r = (const float*)d_in[2];
    const float* Wh_r = (const float*)d_in[3];
    const float* bh_r = (const float*)d_in[4];
    const float* Wi_z = (const float*)d_in[5];
    const float* Wh_z = (const float*)d_in[6];
    const float* bh_z = (const float*)d_in[7];
    const float* Wi_n = (const float*)d_in[8];
    const float* Wh_n = (const float*)d_in[9];
    const float* bh_n = (const float*)d_in[10];
    const float* Wm   = (const float*)d_in[11];
    const float* bm   = (const float*)d_in[12];

    int N = in_sizes[1];  // g has N elements
    float* out   = (float*)d_out;
    float* out_h = out;                       // [N, 8] row-major
    float* out_o = out + (size_t)N * HID;     // [N]

    int blocks = (N + 511) / 512;             // 256 threads x 2 rows each
    l2o_gru_kernel<<<blocks, 256>>>(h, g,
                                    Wi_r, Wh_r, bh_r,
                                    Wi_z, Wh_z, bh_z,
                                    Wi_n, Wh_n, bh_n,
                                    Wm, bm,
                                    out_h, out_o, N);
}

// round 3
// speedup vs baseline: 1.3567x; 1.3567x over previous
#include <cuda_runtime.h>

#define HID 8
typedef unsigned long long u64;

// ---- f32x2 packed helpers (sm_103a) ----
__device__ __forceinline__ u64 pk2(float a, float b) {
    u64 r; asm("mov.b64 %0, {%1, %2};" : "=l"(r) : "f"(a), "f"(b)); return r;
}
__device__ __forceinline__ void upk2(u64 v, float& a, float& b) {
    asm("mov.b64 {%0, %1}, %2;" : "=f"(a), "=f"(b) : "l"(v));
}
__device__ __forceinline__ u64 fma2(u64 a, u64 b, u64 c) {
    u64 d; asm("fma.rn.f32x2 %0, %1, %2, %3;" : "=l"(d) : "l"(a), "l"(b), "l"(c)); return d;
}
__device__ __forceinline__ u64 mul2(u64 a, u64 b) {
    u64 d; asm("mul.rn.f32x2 %0, %1, %2;" : "=l"(d) : "l"(a), "l"(b)); return d;
}
__device__ __forceinline__ u64 add2(u64 a, u64 b) {
    u64 d; asm("add.rn.f32x2 %0, %1, %2;" : "=l"(d) : "l"(a), "l"(b)); return d;
}

__device__ __forceinline__ float tanhap(float x) {
    float y; asm("tanh.approx.f32 %0, %1;" : "=f"(y) : "f"(x)); return y;
}
// sigmoid(x) = 0.5*tanh(x/2) + 0.5  (1 MUFU)
__device__ __forceinline__ u64 sig2(u64 x) {
    float a, b; upk2(x, a, b);
    float ta = tanhap(0.5f * a);
    float tb = tanhap(0.5f * b);
    return pk2(fmaf(0.5f, ta, 0.5f), fmaf(0.5f, tb, 0.5f));
}
__device__ __forceinline__ u64 tanh2p(u64 x) {
    float a, b; upk2(x, a, b);
    return pk2(tanhap(a), tanhap(b));
}

#define LD2(p) (*reinterpret_cast<const u64*>(&(p)))

__global__ void __launch_bounds__(128)
l2o_gru_kernel(const float* __restrict__ h,    const float* __restrict__ g,
               const float* __restrict__ Wi_r, const float* __restrict__ Wh_r, const float* __restrict__ bh_r,
               const float* __restrict__ Wi_z, const float* __restrict__ Wh_z, const float* __restrict__ bh_z,
               const float* __restrict__ Wi_n, const float* __restrict__ Wh_n, const float* __restrict__ bh_n,
               const float* __restrict__ Wm,   const float* __restrict__ bm,
               float* __restrict__ out_h, float* __restrict__ out_o, int N)
{
    // Weights duplicated as (w,w) float2 so LDS.64 broadcast feeds packed FMA directly.
    __shared__ float2 sWh[3][64];   // [gate][k*8+j], gate: 0=r 1=z 2=n
    __shared__ float2 sWi[3][16];
    __shared__ float2 sbh[3][8];
    __shared__ float2 sWm[8];
    __shared__ float  sbm;

    const int t = threadIdx.x;
    if (t < 64) {
        float a = Wh_r[t]; sWh[0][t] = make_float2(a, a);
        float b = Wh_z[t]; sWh[1][t] = make_float2(b, b);
        float c = Wh_n[t]; sWh[2][t] = make_float2(c, c);
    }
    if (t < 16) {
        float a = Wi_r[t]; sWi[0][t] = make_float2(a, a);
        float b = Wi_z[t]; sWi[1][t] = make_float2(b, b);
        float c = Wi_n[t]; sWi[2][t] = make_float2(c, c);
    }
    if (t < 8) {
        float a = bh_r[t]; sbh[0][t] = make_float2(a, a);
        float b = bh_z[t]; sbh[1][t] = make_float2(b, b);
        float c = bh_n[t]; sbh[2][t] = make_float2(c, c);
        float d = Wm[t];   sWm[t]    = make_float2(d, d);
    }
    if (t == 0) sbm = bm[0];
    __syncthreads();

    // Two rows per thread, packed lane-wise: lane0 = rowA, lane1 = rowB.
    const int base = blockIdx.x * 256;
    const int rowA = base + t;
    const int rowB = base + 128 + t;
    const int rA = rowA < N ? rowA : (N - 1);
    const int rB = rowB < N ? rowB : (N - 1);

    // Load h rows (vectorized, coalesced across the warp) and pack.
    u64 hp[HID];
    {
        const float4* pa = reinterpret_cast<const float4*>(h + (size_t)rA * HID);
        const float4* pb = reinterpret_cast<const float4*>(h + (size_t)rB * HID);
        float4 a0 = __ldg(pa), a1 = __ldg(pa + 1);
        float4 b0 = __ldg(pb), b1 = __ldg(pb + 1);
        hp[0] = pk2(a0.x, b0.x); hp[1] = pk2(a0.y, b0.y);
        hp[2] = pk2(a0.z, b0.z); hp[3] = pk2(a0.w, b0.w);
        hp[4] = pk2(a1.x, b1.x); hp[5] = pk2(a1.y, b1.y);
        hp[6] = pk2(a1.z, b1.z); hp[7] = pk2(a1.w, b1.w);
    }

    // Gradient preprocessing (scalar per row, then pack).
    float gA = __ldg(g + rA);
    float gB = __ldg(g + rB);
    u64 gi0, gi1;
    {
        float glA = __logf(fabsf(gA) + 1e-8f) * 0.1f;
        float glB = __logf(fabsf(gB) + 1e-8f) * 0.1f;
        float sA = (gA > 0.0f) ? 1.0f : ((gA < 0.0f) ? -1.0f : 0.0f);
        float sB = (gB > 0.0f) ? 1.0f : ((gB < 0.0f) ? -1.0f : 0.0f);
        const float EXPP = 22026.4658203125f;  // exp(10)
        float i0A, i1A, i0B, i1B;
        if (glA >= -1.0f) { i0A = glA;  i1A = sA; }
        else              { i0A = -1.0f; i1A = EXPP * gA; }
        if (glB >= -1.0f) { i0B = glB;  i1B = sB; }
        else              { i0B = -1.0f; i1B = EXPP * gB; }
        gi0 = pk2(i0A, i0B);
        gi1 = pk2(i1A, i1B);
    }

    u64 outs2;
    { float b0 = sbm; outs2 = pk2(b0, b0); }

    float hnA[HID], hnB[HID];

    #pragma unroll
    for (int j = 0; j < HID; j++) {
        // r gate pre-activation
        u64 ar = fma2(gi1, LD2(sWi[0][HID + j]), fma2(gi0, LD2(sWi[0][j]), LD2(sbh[0][j])));
        // z gate pre-activation
        u64 az = fma2(gi1, LD2(sWi[1][HID + j]), fma2(gi0, LD2(sWi[1][j]), LD2(sbh[1][j])));
        // hidden part of candidate: h @ Wh_n + bh_n
        u64 an = LD2(sbh[2][j]);
        #pragma unroll
        for (int k = 0; k < HID; k++) {
            u64 hk = hp[k];
            ar = fma2(hk, LD2(sWh[0][k * HID + j]), ar);
            az = fma2(hk, LD2(sWh[1][k * HID + j]), az);
            an = fma2(hk, LD2(sWh[2][k * HID + j]), an);
        }
        u64 r2 = sig2(ar);
        u64 z2 = sig2(az);
        u64 win = fma2(gi1, LD2(sWi[2][HID + j]), mul2(gi0, LD2(sWi[2][j])));
        u64 n2 = tanh2p(fma2(r2, an, win));
        // h_new = (1-z)*n + z*h = n + z*(h - n)
        u64 nn = n2 ^ 0x8000000080000000ULL;           // -n (packed sign flip)
        u64 hn2 = fma2(z2, add2(hp[j], nn), n2);
        outs2 = fma2(hn2, LD2(sWm[j]), outs2);
        upk2(hn2, hnA[j], hnB[j]);
    }

    // Stores (vectorized, guarded)
    if (rowA < N) {
        float4* op = reinterpret_cast<float4*>(out_h + (size_t)rowA * HID);
        op[0] = make_float4(hnA[0], hnA[1], hnA[2], hnA[3]);
        op[1] = make_float4(hnA[4], hnA[5], hnA[6], hnA[7]);
    }
    if (rowB < N) {
        float4* op = reinterpret_cast<float4*>(out_h + (size_t)rowB * HID);
        op[0] = make_float4(hnB[0], hnB[1], hnB[2], hnB[3]);
        op[1] = make_float4(hnB[4], hnB[5], hnB[6], hnB[7]);
    }
    float oA, oB;
    upk2(outs2, oA, oB);
    if (rowA < N) out_o[rowA] = -__expf(oA) * gA;
    if (rowB < N) out_o[rowB] = -__expf(oB) * gB;
}

extern "C" void kernel_launch(void* const* d_in, const int* in_sizes, int n_in,
                              void* d_out, int out_size) {
    const float* h    = (const float*)d_in[0];
    const float* g    = (const float*)d_in[1];
    const float* Wi_r = (const float*)d_in[2];
    const float* Wh_r = (const float*)d_in[3];
    const float* bh_r = (const float*)d_in[4];
    const float* Wi_z = (const float*)d_in[5];
    const float* Wh_z = (const float*)d_in[6];
    const float* bh_z = (const float*)d_in[7];
    const float* Wi_n = (const float*)d_in[8];
    const float* Wh_n = (const float*)d_in[9];
    const float* bh_n = (const float*)d_in[10];
    const float* Wm   = (const float*)d_in[11];
    const float* bm   = (const float*)d_in[12];

    int N = in_sizes[1];  // g has N elements
    float* out   = (float*)d_out;
    float* out_h = out;                       // [N, 8] row-major
    float* out_o = out + (size_t)N * HID;     // [N]

    int blocks = (N + 255) / 256;             // 128 threads x 2 rows each
    l2o_gru_kernel<<<blocks, 128>>>(h, g,
                                    Wi_r, Wh_r, bh_r,
                                    Wi_z, Wh_z, bh_z,
                                    Wi_n, Wh_n, bh_n,
                                    Wm, bm,
                                    out_h, out_o, N);
}

// round 7
// speedup vs baseline: 1.4810x; 1.0916x over previous
#include <cuda_runtime.h>

#define HID 8
typedef unsigned long long u64;
typedef unsigned int u32;

// ---- f32x2 packed helpers (sm_103a) ----
__device__ __forceinline__ u64 pk2(float a, float b) {
    u64 r; asm("mov.b64 %0, {%1, %2};" : "=l"(r) : "f"(a), "f"(b)); return r;
}
__device__ __forceinline__ void upk2(u64 v, float& a, float& b) {
    asm("mov.b64 {%0, %1}, %2;" : "=f"(a), "=f"(b) : "l"(v));
}
__device__ __forceinline__ u64 fma2(u64 a, u64 b, u64 c) {
    u64 d; asm("fma.rn.f32x2 %0, %1, %2, %3;" : "=l"(d) : "l"(a), "l"(b), "l"(c)); return d;
}
__device__ __forceinline__ u64 mul2(u64 a, u64 b) {
    u64 d; asm("mul.rn.f32x2 %0, %1, %2;" : "=l"(d) : "l"(a), "l"(b)); return d;
}
__device__ __forceinline__ float tanhap(float x) {
    float y; asm("tanh.approx.f32 %0, %1;" : "=f"(y) : "f"(x)); return y;
}
// Vector shared load: two packed weights (16B) per instruction, pair-aligned.
__device__ __forceinline__ void lds2(u64& a, u64& b, u32 addr) {
    asm volatile("ld.shared.v2.u64 {%0, %1}, [%2];" : "=l"(a), "=l"(b) : "r"(addr));
}

// Per-column weight record, 34 u64 entries (272 B), in exact consumption order:
//  0: bh_r[j]   1: Wi_r[0][j]  2: Wi_r[1][j]   3..10: Wh_r[k][j]
// 11: bh_z[j]  12: Wi_z[0][j] 13: Wi_z[1][j]  14..21: Wh_z[k][j]
// 22: bh_n[j]  23: Wi_n[0][j] 24: Wi_n[1][j]  25..32: Wh_n[k][j]
// 33: Wm[j]
#define REC_U64 34
#define REC_BYTES (REC_U64 * 8)
#define REC_TOTAL (8 * REC_U64)   // 272 entries

__global__ void __launch_bounds__(256, 3)
l2o_gru_kernel(const float* __restrict__ h,    const float* __restrict__ g,
               const float* __restrict__ Wi_r, const float* __restrict__ Wh_r, const float* __restrict__ bh_r,
               const float* __restrict__ Wi_z, const float* __restrict__ Wh_z, const float* __restrict__ bh_z,
               const float* __restrict__ Wi_n, const float* __restrict__ Wh_n, const float* __restrict__ bh_n,
               const float* __restrict__ Wm,   const float* __restrict__ bm,
               float* __restrict__ out_h, float* __restrict__ out_o, int N)
{
    __shared__ __align__(16) float2 srec[REC_TOTAL];
    __shared__ float sbm;

    const int t = threadIdx.x;
    // NOTE: REC_TOTAL (272) > blockDim (256) -> must stride.
    for (int e = t; e < REC_TOTAL; e += 256) {
        int j = e / REC_U64;
        int i = e % REC_U64;
        float w;
        if      (i == 0)  w = bh_r[j];
        else if (i == 1)  w = Wi_r[j];
        else if (i == 2)  w = Wi_r[HID + j];
        else if (i < 11)  w = Wh_r[(i - 3) * HID + j];
        else if (i == 11) w = bh_z[j];
        else if (i == 12) w = Wi_z[j];
        else if (i == 13) w = Wi_z[HID + j];
        else if (i < 22)  w = Wh_z[(i - 14) * HID + j];
        else if (i == 22) w = bh_n[j];
        else if (i == 23) w = Wi_n[j];
        else if (i == 24) w = Wi_n[HID + j];
        else if (i < 33)  w = Wh_n[(i - 25) * HID + j];
        else              w = Wm[j];
        srec[e] = make_float2(w, w);
    }
    if (t == 0) sbm = bm[0];
    __syncthreads();

    const u32 sb = (u32)__cvta_generic_to_shared(srec);

    // Two rows per thread, packed lane-wise: lo = rowA, hi = rowB.
    const int base = blockIdx.x * 512;
    const int rowA = base + t;
    const int rowB = base + 256 + t;
    const int rA = rowA < N ? rowA : (N - 1);
    const int rB = rowB < N ? rowB : (N - 1);

    u64 hp[HID];
    {
        const float4* pa = reinterpret_cast<const float4*>(h + (size_t)rA * HID);
        const float4* pb = reinterpret_cast<const float4*>(h + (size_t)rB * HID);
        float4 a0 = __ldg(pa), a1 = __ldg(pa + 1);
        float4 b0 = __ldg(pb), b1 = __ldg(pb + 1);
        hp[0] = pk2(a0.x, b0.x); hp[1] = pk2(a0.y, b0.y);
        hp[2] = pk2(a0.z, b0.z); hp[3] = pk2(a0.w, b0.w);
        hp[4] = pk2(a1.x, b1.x); hp[5] = pk2(a1.y, b1.y);
        hp[6] = pk2(a1.z, b1.z); hp[7] = pk2(a1.w, b1.w);
    }

    float gA = __ldg(g + rA);
    float gB = __ldg(g + rB);
    u64 gi0, gi1;
    {
        float glA = __logf(fabsf(gA) + 1e-8f) * 0.1f;
        float glB = __logf(fabsf(gB) + 1e-8f) * 0.1f;
        float sA = (gA > 0.0f) ? 1.0f : ((gA < 0.0f) ? -1.0f : 0.0f);
        float sB = (gB > 0.0f) ? 1.0f : ((gB < 0.0f) ? -1.0f : 0.0f);
        const float EXPP = 22026.4658203125f;  // exp(10)
        float i0A, i1A, i0B, i1B;
        if (glA >= -1.0f) { i0A = glA;  i1A = sA; }
        else              { i0A = -1.0f; i1A = EXPP * gA; }
        if (glB >= -1.0f) { i0B = glB;  i1B = sB; }
        else              { i0B = -1.0f; i1B = EXPP * gB; }
        gi0 = pk2(i0A, i0B);
        gi1 = pk2(i1A, i1B);
    }

    float outsA = sbm, outsB = sbm;
    float hnA[HID], hnB[HID];

    #pragma unroll
    for (int j = 0; j < HID; j++) {
        const u32 a = sb + j * REC_BYTES;
        u64 w0, w1, w2, w3;

        // r gate: entries 0..10
        lds2(w0, w1, a);            // bh_r, Wi_r0
        lds2(w2, w3, a + 16);       // Wi_r1, Whr_k0
        u64 ar = fma2(gi0, w1, w0);
        ar = fma2(gi1, w2, ar);
        ar = fma2(hp[0], w3, ar);
        lds2(w0, w1, a + 32);  ar = fma2(hp[1], w0, ar); ar = fma2(hp[2], w1, ar);
        lds2(w2, w3, a + 48);  ar = fma2(hp[3], w2, ar); ar = fma2(hp[4], w3, ar);
        lds2(w0, w1, a + 64);  ar = fma2(hp[5], w0, ar); ar = fma2(hp[6], w1, ar);
        lds2(w2, w3, a + 80);  ar = fma2(hp[7], w2, ar); // w3 = bh_z

        // z gate: entries 12..21
        lds2(w0, w1, a + 96);       // Wi_z0, Wi_z1
        u64 az = fma2(gi0, w0, w3);
        az = fma2(gi1, w1, az);
        lds2(w2, w3, a + 112); az = fma2(hp[0], w2, az); az = fma2(hp[1], w3, az);
        lds2(w0, w1, a + 128); az = fma2(hp[2], w0, az); az = fma2(hp[3], w1, az);
        lds2(w2, w3, a + 144); az = fma2(hp[4], w2, az); az = fma2(hp[5], w3, az);
        lds2(w0, w1, a + 160); az = fma2(hp[6], w0, az); az = fma2(hp[7], w1, az);

        // n gate: entries 22..33
        lds2(w2, w3, a + 176);      // bh_n, Wi_n0
        u64 win = mul2(gi0, w3);
        lds2(w0, w1, a + 192);      // Wi_n1, Whn_k0
        win = fma2(gi1, w0, win);
        u64 an = fma2(hp[0], w1, w2);
        lds2(w2, w3, a + 208); an = fma2(hp[1], w2, an); an = fma2(hp[2], w3, an);
        lds2(w0, w1, a + 224); an = fma2(hp[3], w0, an); an = fma2(hp[4], w1, an);
        lds2(w2, w3, a + 240); an = fma2(hp[5], w2, an); an = fma2(hp[6], w3, an);
        lds2(w0, w1, a + 256); an = fma2(hp[7], w0, an); // w1 = Wm[j] packed

        // scalar epilogue (no repacking)
        float arA, arB, azA, azB, anA, anB, winA, winB, wmA, wmB, hA, hB;
        upk2(ar, arA, arB);
        upk2(az, azA, azB);
        upk2(an, anA, anB);
        upk2(win, winA, winB);
        upk2(w1, wmA, wmB);
        upk2(hp[j], hA, hB);

        float rrA = fmaf(0.5f, tanhap(0.5f * arA), 0.5f);
        float rrB = fmaf(0.5f, tanhap(0.5f * arB), 0.5f);
        float zzA = fmaf(0.5f, tanhap(0.5f * azA), 0.5f);
        float zzB = fmaf(0.5f, tanhap(0.5f * azB), 0.5f);
        float nA = tanhap(fmaf(rrA, anA, winA));
        float nB = tanhap(fmaf(rrB, anB, winB));
        float hnewA = fmaf(zzA, hA - nA, nA);
        float hnewB = fmaf(zzB, hB - nB, nB);
        hnA[j] = hnewA;
        hnB[j] = hnewB;
        outsA = fmaf(hnewA, wmA, outsA);
        outsB = fmaf(hnewB, wmB, outsB);
    }

    if (rowA < N) {
        float4* op = reinterpret_cast<float4*>(out_h + (size_t)rowA * HID);
        op[0] = make_float4(hnA[0], hnA[1], hnA[2], hnA[3]);
        op[1] = make_float4(hnA[4], hnA[5], hnA[6], hnA[7]);
        out_o[rowA] = -__expf(outsA) * gA;
    }
    if (rowB < N) {
        float4* op = reinterpret_cast<float4*>(out_h + (size_t)rowB * HID);
        op[0] = make_float4(hnB[0], hnB[1], hnB[2], hnB[3]);
        op[1] = make_float4(hnB[4], hnB[5], hnB[6], hnB[7]);
        out_o[rowB] = -__expf(outsB) * gB;
    }
}

extern "C" void kernel_launch(void* const* d_in, const int* in_sizes, int n_in,
                              void* d_out, int out_size) {
    const float* h    = (const float*)d_in[0];
    const float* g    = (const float*)d_in[1];
    const float* Wi_r = (const float*)d_in[2];
    const float* Wh_r = (const float*)d_in[3];
    const float* bh_r = (const float*)d_in[4];
    const float* Wi_z = (const float*)d_in[5];
    const float* Wh_z = (const float*)d_in[6];
    const float* bh_z = (const float*)d_in[7];
    const float* Wi_n = (const float*)d_in[8];
    const float* Wh_n = (const float*)d_in[9];
    const float* bh_n = (const float*)d_in[10];
    const float* Wm   = (const float*)d_in[11];
    const float* bm   = (const float*)d_in[12];

    int N = in_sizes[1];  // g has N elements
    float* out   = (float*)d_out;
    float* out_h = out;                       // [N, 8] row-major
    float* out_o = out + (size_t)N * HID;     // [N]

    int blocks = (N + 511) / 512;             // 256 threads x 2 rows each
    l2o_gru_kernel<<<blocks, 256>>>(h, g,
                                    Wi_r, Wh_r, bh_r,
                                    Wi_z, Wh_z, bh_z,
                                    Wi_n, Wh_n, bh_n,
                                    Wm, bm,
                                    out_h, out_o, N);
}

// round 10
// speedup vs baseline: 1.5853x; 1.0704x over previous
#include <cuda_runtime.h>

#define HID 8
typedef unsigned long long u64;
typedef unsigned int u32;

// ---- f32x2 packed helpers (sm_103a) ----
__device__ __forceinline__ u64 pk2(float a, float b) {
    u64 r; asm("mov.b64 %0, {%1, %2};" : "=l"(r) : "f"(a), "f"(b)); return r;
}
__device__ __forceinline__ void upk2(u64 v, float& a, float& b) {
    asm("mov.b64 {%0, %1}, %2;" : "=f"(a), "=f"(b) : "l"(v));
}
__device__ __forceinline__ u64 fma2(u64 a, u64 b, u64 c) {
    u64 d; asm("fma.rn.f32x2 %0, %1, %2, %3;" : "=l"(d) : "l"(a), "l"(b), "l"(c)); return d;
}
__device__ __forceinline__ u64 mul2(u64 a, u64 b) {
    u64 d; asm("mul.rn.f32x2 %0, %1, %2;" : "=l"(d) : "l"(a), "l"(b)); return d;
}
__device__ __forceinline__ float tanhap(float x) {
    float y; asm("tanh.approx.f32 %0, %1;" : "=f"(y) : "f"(x)); return y;
}
// Vector shared load: two packed weights (16B) per instruction, pair-aligned.
__device__ __forceinline__ void lds2(u64& a, u64& b, u32 addr) {
    asm volatile("ld.shared.v2.u64 {%0, %1}, [%2];" : "=l"(a), "=l"(b) : "r"(addr));
}

// Per-column weight record, 34 u64 entries (272 B), in exact consumption order:
//  0: bh_r[j]   1: Wi_r[0][j]  2: Wi_r[1][j]   3..10: Wh_r[k][j]
// 11: bh_z[j]  12: Wi_z[0][j] 13: Wi_z[1][j]  14..21: Wh_z[k][j]
// 22: bh_n[j]  23: Wi_n[0][j] 24: Wi_n[1][j]  25..32: Wh_n[k][j]
// 33: Wm[j]
#define REC_U64 34
#define REC_BYTES (REC_U64 * 8)
#define REC_TOTAL (8 * REC_U64)   // 272 entries

#define TPB 128
#define ROWS_PER_BLOCK (TPB * 4)

__global__ void __launch_bounds__(TPB, 4)
l2o_gru_kernel(const float* __restrict__ h,    const float* __restrict__ g,
               const float* __restrict__ Wi_r, const float* __restrict__ Wh_r, const float* __restrict__ bh_r,
               const float* __restrict__ Wi_z, const float* __restrict__ Wh_z, const float* __restrict__ bh_z,
               const float* __restrict__ Wi_n, const float* __restrict__ Wh_n, const float* __restrict__ bh_n,
               const float* __restrict__ Wm,   const float* __restrict__ bm,
               float* __restrict__ out_h, float* __restrict__ out_o, int N)
{
    __shared__ __align__(16) float2 srec[REC_TOTAL];
    __shared__ float sbm;

    const int t = threadIdx.x;
    for (int e = t; e < REC_TOTAL; e += TPB) {
        int j = e / REC_U64;
        int i = e % REC_U64;
        float w;
        if      (i == 0)  w = bh_r[j];
        else if (i == 1)  w = Wi_r[j];
        else if (i == 2)  w = Wi_r[HID + j];
        else if (i < 11)  w = Wh_r[(i - 3) * HID + j];
        else if (i == 11) w = bh_z[j];
        else if (i == 12) w = Wi_z[j];
        else if (i == 13) w = Wi_z[HID + j];
        else if (i < 22)  w = Wh_z[(i - 14) * HID + j];
        else if (i == 22) w = bh_n[j];
        else if (i == 23) w = Wi_n[j];
        else if (i == 24) w = Wi_n[HID + j];
        else if (i < 33)  w = Wh_n[(i - 25) * HID + j];
        else              w = Wm[j];
        srec[e] = make_float2(w, w);
    }
    if (t == 0) sbm = bm[0];
    __syncthreads();

    const u32 sb = (u32)__cvta_generic_to_shared(srec);

    // Four rows per thread as two lane-packed pairs P=(r0,r1), Q=(r2,r3).
    const int base = blockIdx.x * ROWS_PER_BLOCK;
    int row[4];
    row[0] = base + t;
    row[1] = base + TPB + t;
    row[2] = base + 2 * TPB + t;
    row[3] = base + 3 * TPB + t;
    int rc[4];
    #pragma unroll
    for (int i = 0; i < 4; i++) rc[i] = row[i] < N ? row[i] : (N - 1);

    u64 hP[HID], hQ[HID];
    {
        const float4* p0 = reinterpret_cast<const float4*>(h + (size_t)rc[0] * HID);
        const float4* p1 = reinterpret_cast<const float4*>(h + (size_t)rc[1] * HID);
        float4 a0 = __ldg(p0), a1 = __ldg(p0 + 1);
        float4 b0 = __ldg(p1), b1 = __ldg(p1 + 1);
        hP[0] = pk2(a0.x, b0.x); hP[1] = pk2(a0.y, b0.y);
        hP[2] = pk2(a0.z, b0.z); hP[3] = pk2(a0.w, b0.w);
        hP[4] = pk2(a1.x, b1.x); hP[5] = pk2(a1.y, b1.y);
        hP[6] = pk2(a1.z, b1.z); hP[7] = pk2(a1.w, b1.w);
        const float4* p2 = reinterpret_cast<const float4*>(h + (size_t)rc[2] * HID);
        const float4* p3 = reinterpret_cast<const float4*>(h + (size_t)rc[3] * HID);
        float4 c0 = __ldg(p2), c1 = __ldg(p2 + 1);
        float4 d0 = __ldg(p3), d1 = __ldg(p3 + 1);
        hQ[0] = pk2(c0.x, d0.x); hQ[1] = pk2(c0.y, d0.y);
        hQ[2] = pk2(c0.z, d0.z); hQ[3] = pk2(c0.w, d0.w);
        hQ[4] = pk2(c1.x, d1.x); hQ[5] = pk2(c1.y, d1.y);
        hQ[6] = pk2(c1.z, d1.z); hQ[7] = pk2(c1.w, d1.w);
    }

    float gv[4];
    #pragma unroll
    for (int i = 0; i < 4; i++) gv[i] = __ldg(g + rc[i]);

    u64 gP0, gP1, gQ0, gQ1;
    {
        const float EXPP = 22026.4658203125f;  // exp(10)
        float i0[4], i1[4];
        #pragma unroll
        for (int i = 0; i < 4; i++) {
            float gl = __logf(fabsf(gv[i]) + 1e-8f) * 0.1f;
            float sg = (gv[i] > 0.0f) ? 1.0f : ((gv[i] < 0.0f) ? -1.0f : 0.0f);
            if (gl >= -1.0f) { i0[i] = gl;    i1[i] = sg; }
            else             { i0[i] = -1.0f; i1[i] = EXPP * gv[i]; }
        }
        gP0 = pk2(i0[0], i0[1]); gP1 = pk2(i1[0], i1[1]);
        gQ0 = pk2(i0[2], i0[3]); gQ1 = pk2(i1[2], i1[3]);
    }

    float outs[4] = { sbm, sbm, sbm, sbm };
    float hn0[HID], hn1[HID], hn2[HID], hn3[HID];

    #pragma unroll
    for (int j = 0; j < HID; j++) {
        const u32 a = sb + j * REC_BYTES;
        u64 w0, w1, w2, w3;
        u64 arP, azP, anP, winP, arQ, azQ, anQ, winQ;

        // r gate: entries 0..10
        lds2(w0, w1, a);            // bh_r, Wi_r0
        lds2(w2, w3, a + 16);       // Wi_r1, Whr_k0
        arP = fma2(gP0, w1, w0);            arQ = fma2(gQ0, w1, w0);
        arP = fma2(gP1, w2, arP);           arQ = fma2(gQ1, w2, arQ);
        arP = fma2(hP[0], w3, arP);         arQ = fma2(hQ[0], w3, arQ);
        lds2(w0, w1, a + 32);
        arP = fma2(hP[1], w0, arP);         arQ = fma2(hQ[1], w0, arQ);
        arP = fma2(hP[2], w1, arP);         arQ = fma2(hQ[2], w1, arQ);
        lds2(w2, w3, a + 48);
        arP = fma2(hP[3], w2, arP);         arQ = fma2(hQ[3], w2, arQ);
        arP = fma2(hP[4], w3, arP);         arQ = fma2(hQ[4], w3, arQ);
        lds2(w0, w1, a + 64);
        arP = fma2(hP[5], w0, arP);         arQ = fma2(hQ[5], w0, arQ);
        arP = fma2(hP[6], w1, arP);         arQ = fma2(hQ[6], w1, arQ);
        lds2(w2, w3, a + 80);
        arP = fma2(hP[7], w2, arP);         arQ = fma2(hQ[7], w2, arQ);  // w3 = bh_z

        // z gate: entries 12..21
        lds2(w0, w1, a + 96);       // Wi_z0, Wi_z1
        azP = fma2(gP0, w0, w3);            azQ = fma2(gQ0, w0, w3);
        azP = fma2(gP1, w1, azP);           azQ = fma2(gQ1, w1, azQ);
        lds2(w2, w3, a + 112);
        azP = fma2(hP[0], w2, azP);         azQ = fma2(hQ[0], w2, azQ);
        azP = fma2(hP[1], w3, azP);         azQ = fma2(hQ[1], w3, azQ);
        lds2(w0, w1, a + 128);
        azP = fma2(hP[2], w0, azP);         azQ = fma2(hQ[2], w0, azQ);
        azP = fma2(hP[3], w1, azP);         azQ = fma2(hQ[3], w1, azQ);
        lds2(w2, w3, a + 144);
        azP = fma2(hP[4], w2, azP);         azQ = fma2(hQ[4], w2, azQ);
        azP = fma2(hP[5], w3, azP);         azQ = fma2(hQ[5], w3, azQ);
        lds2(w0, w1, a + 160);
        azP = fma2(hP[6], w0, azP);         azQ = fma2(hQ[6], w0, azQ);
        azP = fma2(hP[7], w1, azP);         azQ = fma2(hQ[7], w1, azQ);

        // n gate: entries 22..33
        lds2(w2, w3, a + 176);      // bh_n, Wi_n0
        winP = mul2(gP0, w3);               winQ = mul2(gQ0, w3);
        lds2(w0, w1, a + 192);      // Wi_n1, Whn_k0
        winP = fma2(gP1, w0, winP);         winQ = fma2(gQ1, w0, winQ);
        anP = fma2(hP[0], w1, w2);          anQ = fma2(hQ[0], w1, w2);
        lds2(w2, w3, a + 208);
        anP = fma2(hP[1], w2, anP);         anQ = fma2(hQ[1], w2, anQ);
        anP = fma2(hP[2], w3, anP);         anQ = fma2(hQ[2], w3, anQ);
        lds2(w0, w1, a + 224);
        anP = fma2(hP[3], w0, anP);         anQ = fma2(hQ[3], w0, anQ);
        anP = fma2(hP[4], w1, anP);         anQ = fma2(hQ[4], w1, anQ);
        lds2(w2, w3, a + 240);
        anP = fma2(hP[5], w2, anP);         anQ = fma2(hQ[5], w2, anQ);
        anP = fma2(hP[6], w3, anP);         anQ = fma2(hQ[6], w3, anQ);
        lds2(w0, w1, a + 256);
        anP = fma2(hP[7], w0, anP);         anQ = fma2(hQ[7], w0, anQ);  // w1 = Wm[j]

        // scalar epilogue (no repacking); Wm unpack shared by both pairs
        float wmA, wmDup; upk2(w1, wmA, wmDup);
        {
            float arA, arB, azA, azB, anA, anB, wiA, wiB, hA, hB;
            upk2(arP, arA, arB); upk2(azP, azA, azB);
            upk2(anP, anA, anB); upk2(winP, wiA, wiB);
            upk2(hP[j], hA, hB);
            float rrA = fmaf(0.5f, tanhap(0.5f * arA), 0.5f);
            float rrB = fmaf(0.5f, tanhap(0.5f * arB), 0.5f);
            float zzA = fmaf(0.5f, tanhap(0.5f * azA), 0.5f);
            float zzB = fmaf(0.5f, tanhap(0.5f * azB), 0.5f);
            float nA = tanhap(fmaf(rrA, anA, wiA));
            float nB = tanhap(fmaf(rrB, anB, wiB));
            float hwA = fmaf(zzA, hA - nA, nA);
            float hwB = fmaf(zzB, hB - nB, nB);
            hn0[j] = hwA; hn1[j] = hwB;
            outs[0] = fmaf(hwA, wmA, outs[0]);
            outs[1] = fmaf(hwB, wmA, outs[1]);
        }
        {
            float arA, arB, azA, azB, anA, anB, wiA, wiB, hA, hB;
            upk2(arQ, arA, arB); upk2(azQ, azA, azB);
            upk2(anQ, anA, anB); upk2(winQ, wiA, wiB);
            upk2(hQ[j], hA, hB);
            float rrA = fmaf(0.5f, tanhap(0.5f * arA), 0.5f);
            float rrB = fmaf(0.5f, tanhap(0.5f * arB), 0.5f);
            float zzA = fmaf(0.5f, tanhap(0.5f * azA), 0.5f);
            float zzB = fmaf(0.5f, tanhap(0.5f * azB), 0.5f);
            float nA = tanhap(fmaf(rrA, anA, wiA));
            float nB = tanhap(fmaf(rrB, anB, wiB));
            float hwA = fmaf(zzA, hA - nA, nA);
            float hwB = fmaf(zzB, hB - nB, nB);
            hn2[j] = hwA; hn3[j] = hwB;
            outs[2] = fmaf(hwA, wmA, outs[2]);
            outs[3] = fmaf(hwB, wmA, outs[3]);
        }
    }

    if (row[0] < N) {
        float4* op = reinterpret_cast<float4*>(out_h + (size_t)row[0] * HID);
        op[0] = make_float4(hn0[0], hn0[1], hn0[2], hn0[3]);
        op[1] = make_float4(hn0[4], hn0[5], hn0[6], hn0[7]);
        out_o[row[0]] = -__expf(outs[0]) * gv[0];
    }
    if (row[1] < N) {
        float4* op = reinterpret_cast<float4*>(out_h + (size_t)row[1] * HID);
        op[0] = make_float4(hn1[0], hn1[1], hn1[2], hn1[3]);
        op[1] = make_float4(hn1[4], hn1[5], hn1[6], hn1[7]);
        out_o[row[1]] = -__expf(outs[1]) * gv[1];
    }
    if (row[2] < N) {
        float4* op = reinterpret_cast<float4*>(out_h + (size_t)row[2] * HID);
        op[0] = make_float4(hn2[0], hn2[1], hn2[2], hn2[3]);
        op[1] = make_float4(hn2[4], hn2[5], hn2[6], hn2[7]);
        out_o[row[2]] = -__expf(outs[2]) * gv[2];
    }
    if (row[3] < N) {
        float4* op = reinterpret_cast<float4*>(out_h + (size_t)row[3] * HID);
        op[0] = make_float4(hn3[0], hn3[1], hn3[2], hn3[3]);
        op[1] = make_float4(hn3[4], hn3[5], hn3[6], hn3[7]);
        out_o[row[3]] = -__expf(outs[3]) * gv[3];
    }
}

extern "C" void kernel_launch(void* const* d_in, const int* in_sizes, int n_in,
                              void* d_out, int out_size) {
    const float* h    = (const float*)d_in[0];
    const float* g    = (const float*)d_in[1];
    const float* Wi_r = (const float*)d_in[2];
    const float* Wh_r = (const float*)d_in[3];
    const float* bh_r = (const float*)d_in[4];
    const float* Wi_z = (const float*)d_in[5];
    const float* Wh_z = (const float*)d_in[6];
    const float* bh_z = (const float*)d_in[7];
    const float* Wi_n = (const float*)d_in[8];
    const float* Wh_n = (const float*)d_in[9];
    const float* bh_n = (const float*)d_in[10];
    const float* Wm   = (const float*)d_in[11];
    const float* bm   = (const float*)d_in[12];

    int N = in_sizes[1];  // g has N elements
    float* out   = (float*)d_out;
    float* out_h = out;                       // [N, 8] row-major
    float* out_o = out + (size_t)N * HID;     // [N]

    int blocks = (N + ROWS_PER_BLOCK - 1) / ROWS_PER_BLOCK;  // 128 thr x 4 rows
    l2o_gru_kernel<<<blocks, TPB>>>(h, g,
                                    Wi_r, Wh_r, bh_r,
                                    Wi_z, Wh_z, bh_z,
                                    Wi_n, Wh_n, bh_n,
                                    Wm, bm,
                                    out_h, out_o, N);
}

// round 11
// speedup vs baseline: 1.6173x; 1.0202x over previous
#include <cuda_runtime.h>

#define HID 8
typedef unsigned long long u64;
typedef unsigned int u32;

// ---- f32x2 packed helpers (sm_103a) ----
__device__ __forceinline__ u64 pk2(float a, float b) {
    u64 r; asm("mov.b64 %0, {%1, %2};" : "=l"(r) : "f"(a), "f"(b)); return r;
}
__device__ __forceinline__ void upk2(u64 v, float& a, float& b) {
    asm("mov.b64 {%0, %1}, %2;" : "=f"(a), "=f"(b) : "l"(v));
}
__device__ __forceinline__ u64 fma2(u64 a, u64 b, u64 c) {
    u64 d; asm("fma.rn.f32x2 %0, %1, %2, %3;" : "=l"(d) : "l"(a), "l"(b), "l"(c)); return d;
}
__device__ __forceinline__ u64 mul2(u64 a, u64 b) {
    u64 d; asm("mul.rn.f32x2 %0, %1, %2;" : "=l"(d) : "l"(a), "l"(b)); return d;
}
// Packed two-lane tanh: intra-asm pair splits are alias-elidable by ptxas.
__device__ __forceinline__ u64 tanh2(u64 x) {
    u64 y;
    asm("{\n\t"
        ".reg .f32 lo, hi, tl, th;\n\t"
        "mov.b64 {lo, hi}, %1;\n\t"
        "tanh.approx.f32 tl, lo;\n\t"
        "tanh.approx.f32 th, hi;\n\t"
        "mov.b64 %0, {tl, th};\n\t"
        "}" : "=l"(y) : "l"(x));
    return y;
}
// Vector shared load: two packed weights (16B) per instruction, pair-aligned.
__device__ __forceinline__ void lds2(u64& a, u64& b, u32 addr) {
    asm volatile("ld.shared.v2.u64 {%0, %1}, [%2];" : "=l"(a), "=l"(b) : "r"(addr));
}

// Per-column weight record, 34 u64 entries (272 B), in exact consumption order:
//  0: bh_r[j]   1: Wi_r[0][j]  2: Wi_r[1][j]   3..10: Wh_r[k][j]
// 11: bh_z[j]  12: Wi_z[0][j] 13: Wi_z[1][j]  14..21: Wh_z[k][j]
// 22: bh_n[j]  23: Wi_n[0][j] 24: Wi_n[1][j]  25..32: Wh_n[k][j]
// 33: Wm[j]
#define REC_U64 34
#define REC_BYTES (REC_U64 * 8)
#define REC_TOTAL (8 * REC_U64)   // 272 entries

#define TPB 128
#define ROWS_PER_BLOCK (TPB * 4)

__global__ void __launch_bounds__(TPB, 4)
l2o_gru_kernel(const float* __restrict__ h,    const float* __restrict__ g,
               const float* __restrict__ Wi_r, const float* __restrict__ Wh_r, const float* __restrict__ bh_r,
               const float* __restrict__ Wi_z, const float* __restrict__ Wh_z, const float* __restrict__ bh_z,
               const float* __restrict__ Wi_n, const float* __restrict__ Wh_n, const float* __restrict__ bh_n,
               const float* __restrict__ Wm,   const float* __restrict__ bm,
               float* __restrict__ out_h, float* __restrict__ out_o, int N)
{
    __shared__ __align__(16) float2 srec[REC_TOTAL];
    __shared__ float sbm;

    const int t = threadIdx.x;
    for (int e = t; e < REC_TOTAL; e += TPB) {
        int j = e / REC_U64;
        int i = e % REC_U64;
        float w;
        if      (i == 0)  w = bh_r[j];
        else if (i == 1)  w = Wi_r[j];
        else if (i == 2)  w = Wi_r[HID + j];
        else if (i < 11)  w = Wh_r[(i - 3) * HID + j];
        else if (i == 11) w = bh_z[j];
        else if (i == 12) w = Wi_z[j];
        else if (i == 13) w = Wi_z[HID + j];
        else if (i < 22)  w = Wh_z[(i - 14) * HID + j];
        else if (i == 22) w = bh_n[j];
        else if (i == 23) w = Wi_n[j];
        else if (i == 24) w = Wi_n[HID + j];
        else if (i < 33)  w = Wh_n[(i - 25) * HID + j];
        else              w = Wm[j];
        srec[e] = make_float2(w, w);
    }
    if (t == 0) sbm = bm[0];
    __syncthreads();

    const u32 sb = (u32)__cvta_generic_to_shared(srec);

    // Four rows per thread as two lane-packed pairs P=(r0,r1), Q=(r2,r3).
    const int base = blockIdx.x * ROWS_PER_BLOCK;
    int row[4];
    row[0] = base + t;
    row[1] = base + TPB + t;
    row[2] = base + 2 * TPB + t;
    row[3] = base + 3 * TPB + t;
    int rc[4];
    #pragma unroll
    for (int i = 0; i < 4; i++) rc[i] = row[i] < N ? row[i] : (N - 1);

    u64 hP[HID], hQ[HID];
    {
        const float4* p0 = reinterpret_cast<const float4*>(h + (size_t)rc[0] * HID);
        const float4* p1 = reinterpret_cast<const float4*>(h + (size_t)rc[1] * HID);
        float4 a0 = __ldg(p0), a1 = __ldg(p0 + 1);
        float4 b0 = __ldg(p1), b1 = __ldg(p1 + 1);
        hP[0] = pk2(a0.x, b0.x); hP[1] = pk2(a0.y, b0.y);
        hP[2] = pk2(a0.z, b0.z); hP[3] = pk2(a0.w, b0.w);
        hP[4] = pk2(a1.x, b1.x); hP[5] = pk2(a1.y, b1.y);
        hP[6] = pk2(a1.z, b1.z); hP[7] = pk2(a1.w, b1.w);
        const float4* p2 = reinterpret_cast<const float4*>(h + (size_t)rc[2] * HID);
        const float4* p3 = reinterpret_cast<const float4*>(h + (size_t)rc[3] * HID);
        float4 c0 = __ldg(p2), c1 = __ldg(p2 + 1);
        float4 d0 = __ldg(p3), d1 = __ldg(p3 + 1);
        hQ[0] = pk2(c0.x, d0.x); hQ[1] = pk2(c0.y, d0.y);
        hQ[2] = pk2(c0.z, d0.z); hQ[3] = pk2(c0.w, d0.w);
        hQ[4] = pk2(c1.x, d1.x); hQ[5] = pk2(c1.y, d1.y);
        hQ[6] = pk2(c1.z, d1.z); hQ[7] = pk2(c1.w, d1.w);
    }

    float gv[4];
    #pragma unroll
    for (int i = 0; i < 4; i++) gv[i] = __ldg(g + rc[i]);

    u64 gP0, gP1, gQ0, gQ1;
    {
        const float EXPP = 22026.4658203125f;  // exp(10)
        float i0[4], i1[4];
        #pragma unroll
        for (int i = 0; i < 4; i++) {
            float gl = __logf(fabsf(gv[i]) + 1e-8f) * 0.1f;
            float sg = (gv[i] > 0.0f) ? 1.0f : ((gv[i] < 0.0f) ? -1.0f : 0.0f);
            if (gl >= -1.0f) { i0[i] = gl;    i1[i] = sg; }
            else             { i0[i] = -1.0f; i1[i] = EXPP * gv[i]; }
        }
        gP0 = pk2(i0[0], i0[1]); gP1 = pk2(i1[0], i1[1]);
        gQ0 = pk2(i0[2], i0[3]); gQ1 = pk2(i1[2], i1[3]);
    }

    const u64 half2 = 0x3F0000003F000000ULL;  // (0.5f, 0.5f)
    const u64 neg12 = 0xBF800000BF800000ULL;  // (-1.f, -1.f)

    u64 outsP = pk2(sbm, sbm);
    u64 outsQ = outsP;
    u64 hnP[HID], hnQ[HID];

    #pragma unroll
    for (int j = 0; j < HID; j++) {
        const u32 a = sb + j * REC_BYTES;
        u64 w0, w1, w2, w3;
        u64 arP, azP, anP, winP, arQ, azQ, anQ, winQ;

        // r gate: entries 0..10
        lds2(w0, w1, a);            // bh_r, Wi_r0
        lds2(w2, w3, a + 16);       // Wi_r1, Whr_k0
        arP = fma2(gP0, w1, w0);            arQ = fma2(gQ0, w1, w0);
        arP = fma2(gP1, w2, arP);           arQ = fma2(gQ1, w2, arQ);
        arP = fma2(hP[0], w3, arP);         arQ = fma2(hQ[0], w3, arQ);
        lds2(w0, w1, a + 32);
        arP = fma2(hP[1], w0, arP);         arQ = fma2(hQ[1], w0, arQ);
        arP = fma2(hP[2], w1, arP);         arQ = fma2(hQ[2], w1, arQ);
        lds2(w2, w3, a + 48);
        arP = fma2(hP[3], w2, arP);         arQ = fma2(hQ[3], w2, arQ);
        arP = fma2(hP[4], w3, arP);         arQ = fma2(hQ[4], w3, arQ);
        lds2(w0, w1, a + 64);
        arP = fma2(hP[5], w0, arP);         arQ = fma2(hQ[5], w0, arQ);
        arP = fma2(hP[6], w1, arP);         arQ = fma2(hQ[6], w1, arQ);
        lds2(w2, w3, a + 80);
        arP = fma2(hP[7], w2, arP);         arQ = fma2(hQ[7], w2, arQ);  // w3 = bh_z

        // z gate: entries 12..21
        lds2(w0, w1, a + 96);       // Wi_z0, Wi_z1
        azP = fma2(gP0, w0, w3);            azQ = fma2(gQ0, w0, w3);
        azP = fma2(gP1, w1, azP);           azQ = fma2(gQ1, w1, azQ);
        lds2(w2, w3, a + 112);
        azP = fma2(hP[0], w2, azP);         azQ = fma2(hQ[0], w2, azQ);
        azP = fma2(hP[1], w3, azP);         azQ = fma2(hQ[1], w3, azQ);
        lds2(w0, w1, a + 128);
        azP = fma2(hP[2], w0, azP);         azQ = fma2(hQ[2], w0, azQ);
        azP = fma2(hP[3], w1, azP);         azQ = fma2(hQ[3], w1, azQ);
        lds2(w2, w3, a + 144);
        azP = fma2(hP[4], w2, azP);         azQ = fma2(hQ[4], w2, azQ);
        azP = fma2(hP[5], w3, azP);         azQ = fma2(hQ[5], w3, azQ);
        lds2(w0, w1, a + 160);
        azP = fma2(hP[6], w0, azP);         azQ = fma2(hQ[6], w0, azQ);
        azP = fma2(hP[7], w1, azP);         azQ = fma2(hQ[7], w1, azQ);

        // n gate: entries 22..33
        lds2(w2, w3, a + 176);      // bh_n, Wi_n0
        winP = mul2(gP0, w3);               winQ = mul2(gQ0, w3);
        lds2(w0, w1, a + 192);      // Wi_n1, Whn_k0
        winP = fma2(gP1, w0, winP);         winQ = fma2(gQ1, w0, winQ);
        anP = fma2(hP[0], w1, w2);          anQ = fma2(hQ[0], w1, w2);
        lds2(w2, w3, a + 208);
        anP = fma2(hP[1], w2, anP);         anQ = fma2(hQ[1], w2, anQ);
        anP = fma2(hP[2], w3, anP);         anQ = fma2(hQ[2], w3, anQ);
        lds2(w0, w1, a + 224);
        anP = fma2(hP[3], w0, anP);         anQ = fma2(hQ[3], w0, anQ);
        anP = fma2(hP[4], w1, anP);         anQ = fma2(hQ[4], w1, anQ);
        lds2(w2, w3, a + 240);
        anP = fma2(hP[5], w2, anP);         anQ = fma2(hQ[5], w2, anQ);
        anP = fma2(hP[6], w3, anP);         anQ = fma2(hQ[6], w3, anQ);
        lds2(w0, w1, a + 256);
        anP = fma2(hP[7], w0, anP);         anQ = fma2(hQ[7], w0, anQ);  // w1 = Wm[j]

        // Fully packed epilogue — no unpacking anywhere.
        {
            u64 r2 = fma2(tanh2(mul2(arP, half2)), half2, half2);
            u64 z2 = fma2(tanh2(mul2(azP, half2)), half2, half2);
            u64 n2 = tanh2(fma2(r2, anP, winP));
            u64 hmn = fma2(n2, neg12, hP[j]);        // h - n
            u64 hnw = fma2(z2, hmn, n2);             // n + z*(h-n)
            hnP[j] = hnw;
            outsP = fma2(hnw, w1, outsP);
        }
        {
            u64 r2 = fma2(tanh2(mul2(arQ, half2)), half2, half2);
            u64 z2 = fma2(tanh2(mul2(azQ, half2)), half2, half2);
            u64 n2 = tanh2(fma2(r2, anQ, winQ));
            u64 hmn = fma2(n2, neg12, hQ[j]);
            u64 hnw = fma2(z2, hmn, n2);
            hnQ[j] = hnw;
            outsQ = fma2(hnw, w1, outsQ);
        }
    }

    // Unpack once at store time.
    float f0[HID], f1[HID], f2[HID], f3[HID];
    #pragma unroll
    for (int j = 0; j < HID; j++) {
        upk2(hnP[j], f0[j], f1[j]);
        upk2(hnQ[j], f2[j], f3[j]);
    }
    float o0, o1, o2, o3;
    upk2(outsP, o0, o1);
    upk2(outsQ, o2, o3);

    if (row[0] < N) {
        float4* op = reinterpret_cast<float4*>(out_h + (size_t)row[0] * HID);
        op[0] = make_float4(f0[0], f0[1], f0[2], f0[3]);
        op[1] = make_float4(f0[4], f0[5], f0[6], f0[7]);
        out_o[row[0]] = -__expf(o0) * gv[0];
    }
    if (row[1] < N) {
        float4* op = reinterpret_cast<float4*>(out_h + (size_t)row[1] * HID);
        op[0] = make_float4(f1[0], f1[1], f1[2], f1[3]);
        op[1] = make_float4(f1[4], f1[5], f1[6], f1[7]);
        out_o[row[1]] = -__expf(o1) * gv[1];
    }
    if (row[2] < N) {
        float4* op = reinterpret_cast<float4*>(out_h + (size_t)row[2] * HID);
        op[0] = make_float4(f2[0], f2[1], f2[2], f2[3]);
        op[1] = make_float4(f2[4], f2[5], f2[6], f2[7]);
        out_o[row[2]] = -__expf(o2) * gv[2];
    }
    if (row[3] < N) {
        float4* op = reinterpret_cast<float4*>(out_h + (size_t)row[3] * HID);
        op[0] = make_float4(f3[0], f3[1], f3[2], f3[3]);
        op[1] = make_float4(f3[4], f3[5], f3[6], f3[7]);
        out_o[row[3]] = -__expf(o3) * gv[3];
    }
}

extern "C" void kernel_launch(void* const* d_in, const int* in_sizes, int n_in,
                              void* d_out, int out_size) {
    const float* h    = (const float*)d_in[0];
    const float* g    = (const float*)d_in[1];
    const float* Wi_r = (const float*)d_in[2];
    const float* Wh_r = (const float*)d_in[3];
    const float* bh_r = (const float*)d_in[4];
    const float* Wi_z = (const float*)d_in[5];
    const float* Wh_z = (const float*)d_in[6];
    const float* bh_z = (const float*)d_in[7];
    const float* Wi_n = (const float*)d_in[8];
    const float* Wh_n = (const float*)d_in[9];
    const float* bh_n = (const float*)d_in[10];
    const float* Wm   = (const float*)d_in[11];
    const float* bm   = (const float*)d_in[12];

    int N = in_sizes[1];  // g has N elements
    float* out   = (float*)d_out;
    float* out_h = out;                       // [N, 8] row-major
    float* out_o = out + (size_t)N * HID;     // [N]

    int blocks = (N + ROWS_PER_BLOCK - 1) / ROWS_PER_BLOCK;  // 128 thr x 4 rows
    l2o_gru_kernel<<<blocks, TPB>>>(h, g,
                                    Wi_r, Wh_r, bh_r,
                                    Wi_z, Wh_z, bh_z,
                                    Wi_n, Wh_n, bh_n,
                                    Wm, bm,
                                    out_h, out_o, N);
}

// round 12
// speedup vs baseline: 1.7703x; 1.0946x over previous
#include <cuda_runtime.h>

#define HID 8
typedef unsigned long long u64;
typedef unsigned int u32;

// ---- f32x2 packed helpers (sm_103a) ----
__device__ __forceinline__ u64 pk2(float a, float b) {
    u64 r; asm("mov.b64 %0, {%1, %2};" : "=l"(r) : "f"(a), "f"(b)); return r;
}
__device__ __forceinline__ void upk2(u64 v, float& a, float& b) {
    asm("mov.b64 {%0, %1}, %2;" : "=f"(a), "=f"(b) : "l"(v));
}
__device__ __forceinline__ u64 fma2(u64 a, u64 b, u64 c) {
    u64 d; asm("fma.rn.f32x2 %0, %1, %2, %3;" : "=l"(d) : "l"(a), "l"(b), "l"(c)); return d;
}
__device__ __forceinline__ u64 mul2(u64 a, u64 b) {
    u64 d; asm("mul.rn.f32x2 %0, %1, %2;" : "=l"(d) : "l"(a), "l"(b)); return d;
}
// Packed two-lane tanh (tanh.approx is scalar; pair halves split in-asm).
__device__ __forceinline__ u64 tanh2(u64 x) {
    u64 y;
    asm("{\n\t"
        ".reg .f32 lo, hi, tl, th;\n\t"
        "mov.b64 {lo, hi}, %1;\n\t"
        "tanh.approx.f32 tl, lo;\n\t"
        "tanh.approx.f32 th, hi;\n\t"
        "mov.b64 %0, {tl, th};\n\t"
        "}" : "=l"(y) : "l"(x));
    return y;
}
// Vector shared load: two packed weights (16B) per instruction, pair-aligned.
__device__ __forceinline__ void lds2(u64& a, u64& b, u32 addr) {
    asm volatile("ld.shared.v2.u64 {%0, %1}, [%2];" : "=l"(a), "=l"(b) : "r"(addr));
}

// Per-column weight record, 34 u64 entries (272 B), in exact consumption order:
//  0: bh_r[j]   1: Wi_r[0][j]  2: Wi_r[1][j]   3..10: Wh_r[k][j]
// 11: bh_z[j]  12: Wi_z[0][j] 13: Wi_z[1][j]  14..21: Wh_z[k][j]
// 22: bh_n[j]  23: Wi_n[0][j] 24: Wi_n[1][j]  25..32: Wh_n[k][j]
// 33: Wm[j]
#define REC_U64 34
#define REC_BYTES (REC_U64 * 8)
#define REC_TOTAL (8 * REC_U64)   // 272 entries

#define TPB 128
#define ROWS_PER_BLOCK (TPB * 4)

__global__ void __launch_bounds__(TPB, 5)
l2o_gru_kernel(const float* __restrict__ h,    const float* __restrict__ g,
               const float* __restrict__ Wi_r, const float* __restrict__ Wh_r, const float* __restrict__ bh_r,
               const float* __restrict__ Wi_z, const float* __restrict__ Wh_z, const float* __restrict__ bh_z,
               const float* __restrict__ Wi_n, const float* __restrict__ Wh_n, const float* __restrict__ bh_n,
               const float* __restrict__ Wm,   const float* __restrict__ bm,
               float* __restrict__ out_h, float* __restrict__ out_o, int N)
{
    __shared__ __align__(16) float2 srec[REC_TOTAL];
    __shared__ float sbm;

    const int t = threadIdx.x;
    for (int e = t; e < REC_TOTAL; e += TPB) {
        int j = e / REC_U64;
        int i = e % REC_U64;
        float w;
        if      (i == 0)  w = bh_r[j];
        else if (i == 1)  w = Wi_r[j];
        else if (i == 2)  w = Wi_r[HID + j];
        else if (i < 11)  w = Wh_r[(i - 3) * HID + j];
        else if (i == 11) w = bh_z[j];
        else if (i == 12) w = Wi_z[j];
        else if (i == 13) w = Wi_z[HID + j];
        else if (i < 22)  w = Wh_z[(i - 14) * HID + j];
        else if (i == 22) w = bh_n[j];
        else if (i == 23) w = Wi_n[j];
        else if (i == 24) w = Wi_n[HID + j];
        else if (i < 33)  w = Wh_n[(i - 25) * HID + j];
        else              w = Wm[j];
        srec[e] = make_float2(w, w);
    }
    if (t == 0) sbm = bm[0];
    __syncthreads();

    const u32 sb = (u32)__cvta_generic_to_shared(srec);

    // Four rows per thread as two lane-packed pairs P=(r0,r1), Q=(r2,r3).
    const int base = blockIdx.x * ROWS_PER_BLOCK;
    int row[4];
    row[0] = base + t;
    row[1] = base + TPB + t;
    row[2] = base + 2 * TPB + t;
    row[3] = base + 3 * TPB + t;
    int rc[4];
    #pragma unroll
    for (int i = 0; i < 4; i++) rc[i] = row[i] < N ? row[i] : (N - 1);

    u64 hP[HID], hQ[HID];
    {
        const float4* p0 = reinterpret_cast<const float4*>(h + (size_t)rc[0] * HID);
        const float4* p1 = reinterpret_cast<const float4*>(h + (size_t)rc[1] * HID);
        float4 a0 = __ldg(p0), a1 = __ldg(p0 + 1);
        float4 b0 = __ldg(p1), b1 = __ldg(p1 + 1);
        hP[0] = pk2(a0.x, b0.x); hP[1] = pk2(a0.y, b0.y);
        hP[2] = pk2(a0.z, b0.z); hP[3] = pk2(a0.w, b0.w);
        hP[4] = pk2(a1.x, b1.x); hP[5] = pk2(a1.y, b1.y);
        hP[6] = pk2(a1.z, b1.z); hP[7] = pk2(a1.w, b1.w);
        const float4* p2 = reinterpret_cast<const float4*>(h + (size_t)rc[2] * HID);
        const float4* p3 = reinterpret_cast<const float4*>(h + (size_t)rc[3] * HID);
        float4 c0 = __ldg(p2), c1 = __ldg(p2 + 1);
        float4 d0 = __ldg(p3), d1 = __ldg(p3 + 1);
        hQ[0] = pk2(c0.x, d0.x); hQ[1] = pk2(c0.y, d0.y);
        hQ[2] = pk2(c0.z, d0.z); hQ[3] = pk2(c0.w, d0.w);
        hQ[4] = pk2(c1.x, d1.x); hQ[5] = pk2(c1.y, d1.y);
        hQ[6] = pk2(c1.z, d1.z); hQ[7] = pk2(c1.w, d1.w);
    }

    float gv[4];
    #pragma unroll
    for (int i = 0; i < 4; i++) gv[i] = __ldg(g + rc[i]);

    u64 gP0, gP1, gQ0, gQ1;
    {
        const float EXPP = 22026.4658203125f;  // exp(10)
        float i0[4], i1[4];
        #pragma unroll
        for (int i = 0; i < 4; i++) {
            float gl = __logf(fabsf(gv[i]) + 1e-8f) * 0.1f;
            float sg = (gv[i] > 0.0f) ? 1.0f : ((gv[i] < 0.0f) ? -1.0f : 0.0f);
            if (gl >= -1.0f) { i0[i] = gl;    i1[i] = sg; }
            else             { i0[i] = -1.0f; i1[i] = EXPP * gv[i]; }
        }
        gP0 = pk2(i0[0], i0[1]); gP1 = pk2(i1[0], i1[1]);
        gQ0 = pk2(i0[2], i0[3]); gQ1 = pk2(i1[2], i1[3]);
    }

    const u64 half2 = 0x3F0000003F000000ULL;  // (0.5f, 0.5f)
    const u64 neg12 = 0xBF800000BF800000ULL;  // (-1.f, -1.f)

    u64 outsP = pk2(sbm, sbm);
    u64 outsQ = outsP;
    // Only 4 columns buffered; stores emitted at j==3 and j==7.
    u64 bP[4], bQ[4];

    #pragma unroll
    for (int j = 0; j < HID; j++) {
        const u32 a = sb + j * REC_BYTES;
        u64 w0, w1, w2, w3;
        u64 arP, azP, anP, winP, arQ, azQ, anQ, winQ;

        // r gate: entries 0..10
        lds2(w0, w1, a);            // bh_r, Wi_r0
        lds2(w2, w3, a + 16);       // Wi_r1, Whr_k0
        arP = fma2(gP0, w1, w0);            arQ = fma2(gQ0, w1, w0);
        arP = fma2(gP1, w2, arP);           arQ = fma2(gQ1, w2, arQ);
        arP = fma2(hP[0], w3, arP);         arQ = fma2(hQ[0], w3, arQ);
        lds2(w0, w1, a + 32);
        arP = fma2(hP[1], w0, arP);         arQ = fma2(hQ[1], w0, arQ);
        arP = fma2(hP[2], w1, arP);         arQ = fma2(hQ[2], w1, arQ);
        lds2(w2, w3, a + 48);
        arP = fma2(hP[3], w2, arP);         arQ = fma2(hQ[3], w2, arQ);
        arP = fma2(hP[4], w3, arP);         arQ = fma2(hQ[4], w3, arQ);
        lds2(w0, w1, a + 64);
        arP = fma2(hP[5], w0, arP);         arQ = fma2(hQ[5], w0, arQ);
        arP = fma2(hP[6], w1, arP);         arQ = fma2(hQ[6], w1, arQ);
        lds2(w2, w3, a + 80);
        arP = fma2(hP[7], w2, arP);         arQ = fma2(hQ[7], w2, arQ);  // w3 = bh_z

        // z gate: entries 12..21
        lds2(w0, w1, a + 96);       // Wi_z0, Wi_z1
        azP = fma2(gP0, w0, w3);            azQ = fma2(gQ0, w0, w3);
        azP = fma2(gP1, w1, azP);           azQ = fma2(gQ1, w1, azQ);
        lds2(w2, w3, a + 112);
        azP = fma2(hP[0], w2, azP);         azQ = fma2(hQ[0], w2, azQ);
        azP = fma2(hP[1], w3, azP);         azQ = fma2(hQ[1], w3, azQ);
        lds2(w0, w1, a + 128);
        azP = fma2(hP[2], w0, azP);         azQ = fma2(hQ[2], w0, azQ);
        azP = fma2(hP[3], w1, azP);         azQ = fma2(hQ[3], w1, azQ);
        lds2(w2, w3, a + 144);
        azP = fma2(hP[4], w2, azP);         azQ = fma2(hQ[4], w2, azQ);
        azP = fma2(hP[5], w3, azP);         azQ = fma2(hQ[5], w3, azQ);
        lds2(w0, w1, a + 160);
        azP = fma2(hP[6], w0, azP);         azQ = fma2(hQ[6], w0, azQ);
        azP = fma2(hP[7], w1, azP);         azQ = fma2(hQ[7], w1, azQ);

        // n gate: entries 22..33
        lds2(w2, w3, a + 176);      // bh_n, Wi_n0
        winP = mul2(gP0, w3);               winQ = mul2(gQ0, w3);
        lds2(w0, w1, a + 192);      // Wi_n1, Whn_k0
        winP = fma2(gP1, w0, winP);         winQ = fma2(gQ1, w0, winQ);
        anP = fma2(hP[0], w1, w2);          anQ = fma2(hQ[0], w1, w2);
        lds2(w2, w3, a + 208);
        anP = fma2(hP[1], w2, anP);         anQ = fma2(hQ[1], w2, anQ);
        anP = fma2(hP[2], w3, anP);         anQ = fma2(hQ[2], w3, anQ);
        lds2(w0, w1, a + 224);
        anP = fma2(hP[3], w0, anP);         anQ = fma2(hQ[3], w0, anQ);
        anP = fma2(hP[4], w1, anP);         anQ = fma2(hQ[4], w1, anQ);
        lds2(w2, w3, a + 240);
        anP = fma2(hP[5], w2, anP);         anQ = fma2(hQ[5], w2, anQ);
        anP = fma2(hP[6], w3, anP);         anQ = fma2(hQ[6], w3, anQ);
        lds2(w0, w1, a + 256);
        anP = fma2(hP[7], w0, anP);         anQ = fma2(hQ[7], w0, anQ);  // w1 = Wm[j]

        // Fully packed epilogue.
        {
            u64 r2 = fma2(tanh2(mul2(arP, half2)), half2, half2);
            u64 z2 = fma2(tanh2(mul2(azP, half2)), half2, half2);
            u64 n2 = tanh2(fma2(r2, anP, winP));
            u64 hmn = fma2(n2, neg12, hP[j]);        // h - n
            u64 hnw = fma2(z2, hmn, n2);             // n + z*(h-n)
            bP[j & 3] = hnw;
            outsP = fma2(hnw, w1, outsP);
        }
        {
            u64 r2 = fma2(tanh2(mul2(arQ, half2)), half2, half2);
            u64 z2 = fma2(tanh2(mul2(azQ, half2)), half2, half2);
            u64 n2 = tanh2(fma2(r2, anQ, winQ));
            u64 hmn = fma2(n2, neg12, hQ[j]);
            u64 hnw = fma2(z2, hmn, n2);
            bQ[j & 3] = hnw;
            outsQ = fma2(hnw, w1, outsQ);
        }

        // Emit half-row stores when a 4-column group completes.
        if (j == 3 || j == 7) {
            const int halfsel = (j == 7);
            float pA0, pB0, pA1, pB1, pA2, pB2, pA3, pB3;
            upk2(bP[0], pA0, pB0); upk2(bP[1], pA1, pB1);
            upk2(bP[2], pA2, pB2); upk2(bP[3], pA3, pB3);
            if (row[0] < N)
                reinterpret_cast<float4*>(out_h + (size_t)row[0] * HID)[halfsel] =
                    make_float4(pA0, pA1, pA2, pA3);
            if (row[1] < N)
                reinterpret_cast<float4*>(out_h + (size_t)row[1] * HID)[halfsel] =
                    make_float4(pB0, pB1, pB2, pB3);
            float qA0, qB0, qA1, qB1, qA2, qB2, qA3, qB3;
            upk2(bQ[0], qA0, qB0); upk2(bQ[1], qA1, qB1);
            upk2(bQ[2], qA2, qB2); upk2(bQ[3], qA3, qB3);
            if (row[2] < N)
                reinterpret_cast<float4*>(out_h + (size_t)row[2] * HID)[halfsel] =
                    make_float4(qA0, qA1, qA2, qA3);
            if (row[3] < N)
                reinterpret_cast<float4*>(out_h + (size_t)row[3] * HID)[halfsel] =
                    make_float4(qB0, qB1, qB2, qB3);
        }
    }

    float o0, o1, o2, o3;
    upk2(outsP, o0, o1);
    upk2(outsQ, o2, o3);
    if (row[0] < N) out_o[row[0]] = -__expf(o0) * gv[0];
    if (row[1] < N) out_o[row[1]] = -__expf(o1) * gv[1];
    if (row[2] < N) out_o[row[2]] = -__expf(o2) * gv[2];
    if (row[3] < N) out_o[row[3]] = -__expf(o3) * gv[3];
}

extern "C" void kernel_launch(void* const* d_in, const int* in_sizes, int n_in,
                              void* d_out, int out_size) {
    const float* h    = (const float*)d_in[0];
    const float* g    = (const float*)d_in[1];
    const float* Wi_r = (const float*)d_in[2];
    const float* Wh_r = (const float*)d_in[3];
    const float* bh_r = (const float*)d_in[4];
    const float* Wi_z = (const float*)d_in[5];
    const float* Wh_z = (const float*)d_in[6];
    const float* bh_z = (const float*)d_in[7];
    const float* Wi_n = (const float*)d_in[8];
    const float* Wh_n = (const float*)d_in[9];
    const float* bh_n = (const float*)d_in[10];
    const float* Wm   = (const float*)d_in[11];
    const float* bm   = (const float*)d_in[12];

    int N = in_sizes[1];  // g has N elements
    float* out   = (float*)d_out;
    float* out_h = out;                       // [N, 8] row-major
    float* out_o = out + (size_t)N * HID;     // [N]

    int blocks = (N + ROWS_PER_BLOCK - 1) / ROWS_PER_BLOCK;  // 128 thr x 4 rows
    l2o_gru_kernel<<<blocks, TPB>>>(h, g,
                                    Wi_r, Wh_r, bh_r,
                                    Wi_z, Wh_z, bh_z,
                                    Wi_n, Wh_n, bh_n,
                                    Wm, bm,
                                    out_h, out_o, N);
}

// round 15
// speedup vs baseline: 2.0866x; 1.1786x over previous
#include <cuda_runtime.h>

#define HID 8
typedef unsigned long long u64;
typedef unsigned int u32;

// ---- f32x2 packed helpers (sm_103a) ----
__device__ __forceinline__ u64 pk2(float a, float b) {
    u64 r; asm("mov.b64 %0, {%1, %2};" : "=l"(r) : "f"(a), "f"(b)); return r;
}
__device__ __forceinline__ void upk2(u64 v, float& a, float& b) {
    asm("mov.b64 {%0, %1}, %2;" : "=f"(a), "=f"(b) : "l"(v));
}
__device__ __forceinline__ u64 fma2(u64 a, u64 b, u64 c) {
    u64 d; asm("fma.rn.f32x2 %0, %1, %2, %3;" : "=l"(d) : "l"(a), "l"(b), "l"(c)); return d;
}
__device__ __forceinline__ u64 mul2(u64 a, u64 b) {
    u64 d; asm("mul.rn.f32x2 %0, %1, %2;" : "=l"(d) : "l"(a), "l"(b)); return d;
}
// Packed two-lane tanh (tanh.approx is scalar; pair halves split in-asm).
__device__ __forceinline__ u64 tanh2(u64 x) {
    u64 y;
    asm("{\n\t"
        ".reg .f32 lo, hi, tl, th;\n\t"
        "mov.b64 {lo, hi}, %1;\n\t"
        "tanh.approx.f32 tl, lo;\n\t"
        "tanh.approx.f32 th, hi;\n\t"
        "mov.b64 %0, {tl, th};\n\t"
        "}" : "=l"(y) : "l"(x));
    return y;
}
// Build (lo(x), lo(y)) — used to turn broadcast h regs back into a column pair.
__device__ __forceinline__ u64 mergelo(u64 x, u64 y) {
    u64 r;
    asm("{\n\t"
        ".reg .f32 xl, xh, yl, yh;\n\t"
        "mov.b64 {xl, xh}, %1;\n\t"
        "mov.b64 {yl, yh}, %2;\n\t"
        "mov.b64 %0, {xl, yl};\n\t"
        "}" : "=l"(r) : "l"(x), "l"(y));
    return r;
}
// Vector shared load: two weight pairs (16B) per instruction.
__device__ __forceinline__ void lds2(u64& a, u64& b, u32 addr) {
    asm volatile("ld.shared.v2.u64 {%0, %1}, [%2];" : "=l"(a), "=l"(b) : "r"(addr));
}

// Per-COLUMN-PAIR weight record (jp = j/2), 34 float2 entries (272 B), natural
// adjacent-column pairs (w[2jp], w[2jp+1]) — NO duplication. Consumption order:
//  0: bh_r   1: Wi_r[0]  2: Wi_r[1]   3..10: Wh_r[k] k=0..7
// 11: bh_z  12: Wi_z[0] 13: Wi_z[1]  14..21: Wh_z[k]
// 22: bh_n  23: Wi_n[0] 24: Wi_n[1]  25..32: Wh_n[k]
// 33: Wm
#define REC_U64 34
#define REC_BYTES (REC_U64 * 8)
#define REC_TOTAL (4 * REC_U64)   // 136 entries (4 column-pair records)

#define TPB 128
#define ROWS_PER_BLOCK (TPB * 2)

__global__ void __launch_bounds__(TPB, 6)
l2o_gru_kernel(const float* __restrict__ h,    const float* __restrict__ g,
               const float* __restrict__ Wi_r, const float* __restrict__ Wh_r, const float* __restrict__ bh_r,
               const float* __restrict__ Wi_z, const float* __restrict__ Wh_z, const float* __restrict__ bh_z,
               const float* __restrict__ Wi_n, const float* __restrict__ Wh_n, const float* __restrict__ bh_n,
               const float* __restrict__ Wm,   const float* __restrict__ bm,
               float* __restrict__ out_h, float* __restrict__ out_o, int N)
{
    __shared__ __align__(16) float2 srec[REC_TOTAL];
    __shared__ float sbm;

    const int t = threadIdx.x;
    // REC_TOTAL (136) > TPB (128): MUST stride, not guard.
    for (int e = t; e < REC_TOTAL; e += TPB) {
        int jp = e / REC_U64;
        int i  = e % REC_U64;
        int c  = 2 * jp;
        const float* src;
        if      (i == 0)  src = bh_r + c;
        else if (i == 1)  src = Wi_r + c;
        else if (i == 2)  src = Wi_r + HID + c;
        else if (i < 11)  src = Wh_r + (i - 3) * HID + c;
        else if (i == 11) src = bh_z + c;
        else if (i == 12) src = Wi_z + c;
        else if (i == 13) src = Wi_z + HID + c;
        else if (i < 22)  src = Wh_z + (i - 14) * HID + c;
        else if (i == 22) src = bh_n + c;
        else if (i == 23) src = Wi_n + c;
        else if (i == 24) src = Wi_n + HID + c;
        else if (i < 33)  src = Wh_n + (i - 25) * HID + c;
        else              src = Wm + c;
        srec[e] = *reinterpret_cast<const float2*>(src);
    }
    if (t == 0) sbm = bm[0];
    __syncthreads();

    const u32 sb = (u32)__cvta_generic_to_shared(srec);

    // Two rows per thread (R, S); lanes of each f32x2 are adjacent COLUMNS.
    const int base = blockIdx.x * ROWS_PER_BLOCK;
    const int rowR = base + t;
    const int rowS = base + TPB + t;
    const int rcR = rowR < N ? rowR : (N - 1);
    const int rcS = rowS < N ? rowS : (N - 1);
    const bool okR = rowR < N;
    const bool okS = rowS < N;

    // Broadcast h registers: hbX[k] = (h[k], h[k]).
    u64 hbR[HID], hbS[HID];
    {
        const float4* p0 = reinterpret_cast<const float4*>(h + (size_t)rcR * HID);
        float4 a0 = __ldg(p0), a1 = __ldg(p0 + 1);
        hbR[0] = pk2(a0.x, a0.x); hbR[1] = pk2(a0.y, a0.y);
        hbR[2] = pk2(a0.z, a0.z); hbR[3] = pk2(a0.w, a0.w);
        hbR[4] = pk2(a1.x, a1.x); hbR[5] = pk2(a1.y, a1.y);
        hbR[6] = pk2(a1.z, a1.z); hbR[7] = pk2(a1.w, a1.w);
        const float4* p1 = reinterpret_cast<const float4*>(h + (size_t)rcS * HID);
        float4 b0 = __ldg(p1), b1 = __ldg(p1 + 1);
        hbS[0] = pk2(b0.x, b0.x); hbS[1] = pk2(b0.y, b0.y);
        hbS[2] = pk2(b0.z, b0.z); hbS[3] = pk2(b0.w, b0.w);
        hbS[4] = pk2(b1.x, b1.x); hbS[5] = pk2(b1.y, b1.y);
        hbS[6] = pk2(b1.z, b1.z); hbS[7] = pk2(b1.w, b1.w);
    }

    float gR = __ldg(g + rcR);
    float gS = __ldg(g + rcS);
    u64 gbR0, gbR1, gbS0, gbS1;
    {
        const float EXPP = 22026.4658203125f;  // exp(10)
        float glR = __logf(fabsf(gR) + 1e-8f) * 0.1f;
        float glS = __logf(fabsf(gS) + 1e-8f) * 0.1f;
        float sgR = (gR > 0.0f) ? 1.0f : ((gR < 0.0f) ? -1.0f : 0.0f);
        float sgS = (gS > 0.0f) ? 1.0f : ((gS < 0.0f) ? -1.0f : 0.0f);
        float i0R, i1R, i0S, i1S;
        if (glR >= -1.0f) { i0R = glR;   i1R = sgR; }
        else              { i0R = -1.0f; i1R = EXPP * gR; }
        if (glS >= -1.0f) { i0S = glS;   i1S = sgS; }
        else              { i0S = -1.0f; i1S = EXPP * gS; }
        gbR0 = pk2(i0R, i0R); gbR1 = pk2(i1R, i1R);
        gbS0 = pk2(i0S, i0S); gbS1 = pk2(i1S, i1S);
    }

    const u64 half2 = 0x3F0000003F000000ULL;  // (0.5f, 0.5f)
    const u64 neg12 = 0xBF800000BF800000ULL;  // (-1.f, -1.f)

    u64 outsR = pk2(sbm, 0.0f);   // bm in even-lane; horizontal add at the end
    u64 outsS = outsR;

    u64* ohR = reinterpret_cast<u64*>(out_h + (size_t)rowR * HID);
    u64* ohS = reinterpret_cast<u64*>(out_h + (size_t)rowS * HID);

    #pragma unroll
    for (int jp = 0; jp < 4; jp++) {
        const u32 a = sb + jp * REC_BYTES;
        u64 w0, w1, w2, w3;
        u64 arR, azR, anR, winR, arS, azS, anS, winS;

        // r gate: entries 0..10
        lds2(w0, w1, a);            // bh_r, Wi_r0
        lds2(w2, w3, a + 16);       // Wi_r1, Whr k0
        arR = fma2(gbR0, w1, w0);           arS = fma2(gbS0, w1, w0);
        arR = fma2(gbR1, w2, arR);          arS = fma2(gbS1, w2, arS);
        arR = fma2(hbR[0], w3, arR);        arS = fma2(hbS[0], w3, arS);
        lds2(w0, w1, a + 32);
        arR = fma2(hbR[1], w0, arR);        arS = fma2(hbS[1], w0, arS);
        arR = fma2(hbR[2], w1, arR);        arS = fma2(hbS[2], w1, arS);
        lds2(w2, w3, a + 48);
        arR = fma2(hbR[3], w2, arR);        arS = fma2(hbS[3], w2, arS);
        arR = fma2(hbR[4], w3, arR);        arS = fma2(hbS[4], w3, arS);
        lds2(w0, w1, a + 64);
        arR = fma2(hbR[5], w0, arR);        arS = fma2(hbS[5], w0, arS);
        arR = fma2(hbR[6], w1, arR);        arS = fma2(hbS[6], w1, arS);
        lds2(w2, w3, a + 80);
        arR = fma2(hbR[7], w2, arR);        arS = fma2(hbS[7], w2, arS);  // w3 = bh_z

        // z gate: entries 12..21
        lds2(w0, w1, a + 96);       // Wi_z0, Wi_z1
        azR = fma2(gbR0, w0, w3);           azS = fma2(gbS0, w0, w3);
        azR = fma2(gbR1, w1, azR);          azS = fma2(gbS1, w1, azS);
        lds2(w2, w3, a + 112);
        azR = fma2(hbR[0], w2, azR);        azS = fma2(hbS[0], w2, azS);
        azR = fma2(hbR[1], w3, azR);        azS = fma2(hbS[1], w3, azS);
        lds2(w0, w1, a + 128);
        azR = fma2(hbR[2], w0, azR);        azS = fma2(hbS[2], w0, azS);
        azR = fma2(hbR[3], w1, azR);        azS = fma2(hbS[3], w1, azS);
        lds2(w2, w3, a + 144);
        azR = fma2(hbR[4], w2, azR);        azS = fma2(hbS[4], w2, azS);
        azR = fma2(hbR[5], w3, azR);        azS = fma2(hbS[5], w3, azS);
        lds2(w0, w1, a + 160);
        azR = fma2(hbR[6], w0, azR);        azS = fma2(hbS[6], w0, azS);
        azR = fma2(hbR[7], w1, azR);        azS = fma2(hbS[7], w1, azS);

        // n gate: entries 22..33
        lds2(w2, w3, a + 176);      // bh_n, Wi_n0
        winR = mul2(gbR0, w3);              winS = mul2(gbS0, w3);
        lds2(w0, w1, a + 192);      // Wi_n1, Whn k0
        winR = fma2(gbR1, w0, winR);        winS = fma2(gbS1, w0, winS);
        anR = fma2(hbR[0], w1, w2);         anS = fma2(hbS[0], w1, w2);
        lds2(w2, w3, a + 208);
        anR = fma2(hbR[1], w2, anR);        anS = fma2(hbS[1], w2, anS);
        anR = fma2(hbR[2], w3, anR);        anS = fma2(hbS[2], w3, anS);
        lds2(w0, w1, a + 224);
        anR = fma2(hbR[3], w0, anR);        anS = fma2(hbS[3], w0, anS);
        anR = fma2(hbR[4], w1, anR);        anS = fma2(hbS[4], w1, anS);
        lds2(w2, w3, a + 240);
        anR = fma2(hbR[5], w2, anR);        anS = fma2(hbS[5], w2, anS);
        anR = fma2(hbR[6], w3, anR);        anS = fma2(hbS[6], w3, anS);
        lds2(w0, w1, a + 256);
        anR = fma2(hbR[7], w0, anR);        anS = fma2(hbS[7], w0, anS);  // w1 = Wm pair

        // Packed epilogue; hn pair is stored DIRECTLY (no unpack).
        {
            u64 r2 = fma2(tanh2(mul2(arR, half2)), half2, half2);
            u64 z2 = fma2(tanh2(mul2(azR, half2)), half2, half2);
            u64 n2 = tanh2(fma2(r2, anR, winR));
            u64 hpr = mergelo(hbR[2 * jp], hbR[2 * jp + 1]);   // (h[2jp], h[2jp+1])
            u64 hn2 = fma2(z2, fma2(n2, neg12, hpr), n2);      // n + z*(h-n)
            if (okR) ohR[jp] = hn2;
            outsR = fma2(hn2, w1, outsR);
        }
        {
            u64 r2 = fma2(tanh2(mul2(arS, half2)), half2, half2);
            u64 z2 = fma2(tanh2(mul2(azS, half2)), half2, half2);
            u64 n2 = tanh2(fma2(r2, anS, winS));
            u64 hps = mergelo(hbS[2 * jp], hbS[2 * jp + 1]);
            u64 hn2 = fma2(z2, fma2(n2, neg12, hps), n2);
            if (okS) ohS[jp] = hn2;
            outsS = fma2(hn2, w1, outsS);
        }
    }

    float eR, oR, eS, oS;
    upk2(outsR, eR, oR);
    upk2(outsS, eS, oS);
    if (okR) out_o[rowR] = -__expf(eR + oR) * gR;
    if (okS) out_o[rowS] = -__expf(eS + oS) * gS;
}

extern "C" void kernel_launch(void* const* d_in, const int* in_sizes, int n_in,
                              void* d_out, int out_size) {
    const float* h    = (const float*)d_in[0];
    const float* g    = (const float*)d_in[1];
    const float* Wi_r = (const float*)d_in[2];
    const float* Wh_r = (const float*)d_in[3];
    const float* bh_r = (const float*)d_in[4];
    const float* Wi_z = (const float*)d_in[5];
    const float* Wh_z = (const float*)d_in[6];
    const float* bh_z = (const float*)d_in[7];
    const float* Wi_n = (const float*)d_in[8];
    const float* Wh_n = (const float*)d_in[9];
    const float* bh_n = (const float*)d_in[10];
    const float* Wm   = (const float*)d_in[11];
    const float* bm   = (const float*)d_in[12];

    int N = in_sizes[1];  // g has N elements
    float* out   = (float*)d_out;
    float* out_h = out;                       // [N, 8] row-major
    float* out_o = out + (size_t)N * HID;     // [N]

    int blocks = (N + ROWS_PER_BLOCK - 1) / ROWS_PER_BLOCK;  // 128 thr x 2 rows
    l2o_gru_kernel<<<blocks, TPB>>>(h, g,
                                    Wi_r, Wh_r, bh_r,
                                    Wi_z, Wh_z, bh_z,
                                    Wi_n, Wh_n, bh_n,
                                    Wm, bm,
                                    out_h, out_o, N);
}

// round 16
// speedup vs baseline: 2.2255x; 1.0666x over previous
#include <cuda_runtime.h>

#define HID 8
typedef unsigned long long u64;
typedef unsigned int u32;

// ---- f32x2 packed helpers (sm_103a) ----
__device__ __forceinline__ u64 pk2(float a, float b) {
    u64 r; asm("mov.b64 %0, {%1, %2};" : "=l"(r) : "f"(a), "f"(b)); return r;
}
__device__ __forceinline__ void upk2(u64 v, float& a, float& b) {
    asm("mov.b64 {%0, %1}, %2;" : "=f"(a), "=f"(b) : "l"(v));
}
__device__ __forceinline__ u64 fma2(u64 a, u64 b, u64 c) {
    u64 d; asm("fma.rn.f32x2 %0, %1, %2, %3;" : "=l"(d) : "l"(a), "l"(b), "l"(c)); return d;
}
__device__ __forceinline__ u64 mul2(u64 a, u64 b) {
    u64 d; asm("mul.rn.f32x2 %0, %1, %2;" : "=l"(d) : "l"(a), "l"(b)); return d;
}
// Packed two-lane tanh (tanh.approx is scalar; pair halves split in-asm).
__device__ __forceinline__ u64 tanh2(u64 x) {
    u64 y;
    asm("{\n\t"
        ".reg .f32 lo, hi, tl, th;\n\t"
        "mov.b64 {lo, hi}, %1;\n\t"
        "tanh.approx.f32 tl, lo;\n\t"
        "tanh.approx.f32 th, hi;\n\t"
        "mov.b64 %0, {tl, th};\n\t"
        "}" : "=l"(y) : "l"(x));
    return y;
}
// Build (lo(x), lo(y)) — used to turn broadcast h regs back into a column pair.
__device__ __forceinline__ u64 mergelo(u64 x, u64 y) {
    u64 r;
    asm("{\n\t"
        ".reg .f32 xl, xh, yl, yh;\n\t"
        "mov.b64 {xl, xh}, %1;\n\t"
        "mov.b64 {yl, yh}, %2;\n\t"
        "mov.b64 %0, {xl, yl};\n\t"
        "}" : "=l"(r) : "l"(x), "l"(y));
    return r;
}
// Vector shared load: two weight pairs (16B) per instruction.
__device__ __forceinline__ void lds2(u64& a, u64& b, u32 addr) {
    asm volatile("ld.shared.v2.u64 {%0, %1}, [%2];" : "=l"(a), "=l"(b) : "r"(addr));
}
// 16B global store of two packed pairs — one STG.128 instead of two STG.64.
__device__ __forceinline__ void stg2(void* p, u64 a, u64 b) {
    asm volatile("st.global.v2.u64 [%0], {%1, %2};" :: "l"(p), "l"(a), "l"(b) : "memory");
}

// Per-COLUMN-PAIR weight record (jp = j/2), 34 float2 entries (272 B), natural
// adjacent-column pairs (w[2jp], w[2jp+1]) — NO duplication. Consumption order:
//  0: bh_r   1: Wi_r[0]  2: Wi_r[1]   3..10: Wh_r[k] k=0..7
// 11: bh_z  12: Wi_z[0] 13: Wi_z[1]  14..21: Wh_z[k]
// 22: bh_n  23: Wi_n[0] 24: Wi_n[1]  25..32: Wh_n[k]
// 33: Wm
#define REC_U64 34
#define REC_BYTES (REC_U64 * 8)
#define REC_TOTAL (4 * REC_U64)   // 136 entries (4 column-pair records)

#define TPB 128
#define ROWS_PER_BLOCK (TPB * 2)

__global__ void __launch_bounds__(TPB, 6)
l2o_gru_kernel(const float* __restrict__ h,    const float* __restrict__ g,
               const float* __restrict__ Wi_r, const float* __restrict__ Wh_r, const float* __restrict__ bh_r,
               const float* __restrict__ Wi_z, const float* __restrict__ Wh_z, const float* __restrict__ bh_z,
               const float* __restrict__ Wi_n, const float* __restrict__ Wh_n, const float* __restrict__ bh_n,
               const float* __restrict__ Wm,   const float* __restrict__ bm,
               float* __restrict__ out_h, float* __restrict__ out_o, int N)
{
    __shared__ __align__(16) float2 srec[REC_TOTAL];
    __shared__ float sbm;

    const int t = threadIdx.x;
    // REC_TOTAL (136) > TPB (128): MUST stride, not guard.
    for (int e = t; e < REC_TOTAL; e += TPB) {
        int jp = e / REC_U64;
        int i  = e % REC_U64;
        int c  = 2 * jp;
        const float* src;
        if      (i == 0)  src = bh_r + c;
        else if (i == 1)  src = Wi_r + c;
        else if (i == 2)  src = Wi_r + HID + c;
        else if (i < 11)  src = Wh_r + (i - 3) * HID + c;
        else if (i == 11) src = bh_z + c;
        else if (i == 12) src = Wi_z + c;
        else if (i == 13) src = Wi_z + HID + c;
        else if (i < 22)  src = Wh_z + (i - 14) * HID + c;
        else if (i == 22) src = bh_n + c;
        else if (i == 23) src = Wi_n + c;
        else if (i == 24) src = Wi_n + HID + c;
        else if (i < 33)  src = Wh_n + (i - 25) * HID + c;
        else              src = Wm + c;
        srec[e] = *reinterpret_cast<const float2*>(src);
    }
    if (t == 0) sbm = bm[0];
    __syncthreads();

    const u32 sb = (u32)__cvta_generic_to_shared(srec);

    // Two rows per thread (R, S); lanes of each f32x2 are adjacent COLUMNS.
    const int base = blockIdx.x * ROWS_PER_BLOCK;
    const int rowR = base + t;
    const int rowS = base + TPB + t;
    const int rcR = rowR < N ? rowR : (N - 1);
    const int rcS = rowS < N ? rowS : (N - 1);
    const bool okR = rowR < N;
    const bool okS = rowS < N;

    // Broadcast h registers: hbX[k] = (h[k], h[k]).
    u64 hbR[HID], hbS[HID];
    {
        const float4* p0 = reinterpret_cast<const float4*>(h + (size_t)rcR * HID);
        float4 a0 = __ldg(p0), a1 = __ldg(p0 + 1);
        hbR[0] = pk2(a0.x, a0.x); hbR[1] = pk2(a0.y, a0.y);
        hbR[2] = pk2(a0.z, a0.z); hbR[3] = pk2(a0.w, a0.w);
        hbR[4] = pk2(a1.x, a1.x); hbR[5] = pk2(a1.y, a1.y);
        hbR[6] = pk2(a1.z, a1.z); hbR[7] = pk2(a1.w, a1.w);
        const float4* p1 = reinterpret_cast<const float4*>(h + (size_t)rcS * HID);
        float4 b0 = __ldg(p1), b1 = __ldg(p1 + 1);
        hbS[0] = pk2(b0.x, b0.x); hbS[1] = pk2(b0.y, b0.y);
        hbS[2] = pk2(b0.z, b0.z); hbS[3] = pk2(b0.w, b0.w);
        hbS[4] = pk2(b1.x, b1.x); hbS[5] = pk2(b1.y, b1.y);
        hbS[6] = pk2(b1.z, b1.z); hbS[7] = pk2(b1.w, b1.w);
    }

    float gR = __ldg(g + rcR);
    float gS = __ldg(g + rcS);
    u64 gbR0, gbR1, gbS0, gbS1;
    {
        const float EXPP = 22026.4658203125f;  // exp(10)
        float glR = __logf(fabsf(gR) + 1e-8f) * 0.1f;
        float glS = __logf(fabsf(gS) + 1e-8f) * 0.1f;
        float sgR = (gR > 0.0f) ? 1.0f : ((gR < 0.0f) ? -1.0f : 0.0f);
        float sgS = (gS > 0.0f) ? 1.0f : ((gS < 0.0f) ? -1.0f : 0.0f);
        float i0R, i1R, i0S, i1S;
        if (glR >= -1.0f) { i0R = glR;   i1R = sgR; }
        else              { i0R = -1.0f; i1R = EXPP * gR; }
        if (glS >= -1.0f) { i0S = glS;   i1S = sgS; }
        else              { i0S = -1.0f; i1S = EXPP * gS; }
        gbR0 = pk2(i0R, i0R); gbR1 = pk2(i1R, i1R);
        gbS0 = pk2(i0S, i0S); gbS1 = pk2(i1S, i1S);
    }

    const u64 half2 = 0x3F0000003F000000ULL;  // (0.5f, 0.5f)
    const u64 neg12 = 0xBF800000BF800000ULL;  // (-1.f, -1.f)

    u64 outsR = pk2(sbm, 0.0f);   // bm in even-lane; horizontal add at the end
    u64 outsS = outsR;

    char* ohR = reinterpret_cast<char*>(out_h + (size_t)rowR * HID);
    char* ohS = reinterpret_cast<char*>(out_h + (size_t)rowS * HID);

    u64 prevR = 0, prevS = 0;   // even-jp hn2, stored at the following odd jp

    #pragma unroll
    for (int jp = 0; jp < 4; jp++) {
        const u32 a = sb + jp * REC_BYTES;
        u64 w0, w1, w2, w3;
        u64 arR, azR, anR, winR, arS, azS, anS, winS;

        // r gate: entries 0..10
        lds2(w0, w1, a);            // bh_r, Wi_r0
        lds2(w2, w3, a + 16);       // Wi_r1, Whr k0
        arR = fma2(gbR0, w1, w0);           arS = fma2(gbS0, w1, w0);
        arR = fma2(gbR1, w2, arR);          arS = fma2(gbS1, w2, arS);
        arR = fma2(hbR[0], w3, arR);        arS = fma2(hbS[0], w3, arS);
        lds2(w0, w1, a + 32);
        arR = fma2(hbR[1], w0, arR);        arS = fma2(hbS[1], w0, arS);
        arR = fma2(hbR[2], w1, arR);        arS = fma2(hbS[2], w1, arS);
        lds2(w2, w3, a + 48);
        arR = fma2(hbR[3], w2, arR);        arS = fma2(hbS[3], w2, arS);
        arR = fma2(hbR[4], w3, arR);        arS = fma2(hbS[4], w3, arS);
        lds2(w0, w1, a + 64);
        arR = fma2(hbR[5], w0, arR);        arS = fma2(hbS[5], w0, arS);
        arR = fma2(hbR[6], w1, arR);        arS = fma2(hbS[6], w1, arS);
        lds2(w2, w3, a + 80);
        arR = fma2(hbR[7], w2, arR);        arS = fma2(hbS[7], w2, arS);  // w3 = bh_z

        // z gate: entries 12..21
        lds2(w0, w1, a + 96);       // Wi_z0, Wi_z1
        azR = fma2(gbR0, w0, w3);           azS = fma2(gbS0, w0, w3);
        azR = fma2(gbR1, w1, azR);          azS = fma2(gbS1, w1, azS);
        lds2(w2, w3, a + 112);
        azR = fma2(hbR[0], w2, azR);        azS = fma2(hbS[0], w2, azS);
        azR = fma2(hbR[1], w3, azR);        azS = fma2(hbS[1], w3, azS);
        lds2(w0, w1, a + 128);
        azR = fma2(hbR[2], w0, azR);        azS = fma2(hbS[2], w0, azS);
        azR = fma2(hbR[3], w1, azR);        azS = fma2(hbS[3], w1, azS);
        lds2(w2, w3, a + 144);
        azR = fma2(hbR[4], w2, azR);        azS = fma2(hbS[4], w2, azS);
        azR = fma2(hbR[5], w3, azR);        azS = fma2(hbS[5], w3, azS);
        lds2(w0, w1, a + 160);
        azR = fma2(hbR[6], w0, azR);        azS = fma2(hbS[6], w0, azS);
        azR = fma2(hbR[7], w1, azR);        azS = fma2(hbS[7], w1, azS);

        // n gate: entries 22..33
        lds2(w2, w3, a + 176);      // bh_n, Wi_n0
        winR = mul2(gbR0, w3);              winS = mul2(gbS0, w3);
        lds2(w0, w1, a + 192);      // Wi_n1, Whn k0
        winR = fma2(gbR1, w0, winR);        winS = fma2(gbS1, w0, winS);
        anR = fma2(hbR[0], w1, w2);         anS = fma2(hbS[0], w1, w2);
        lds2(w2, w3, a + 208);
        anR = fma2(hbR[1], w2, anR);        anS = fma2(hbS[1], w2, anS);
        anR = fma2(hbR[2], w3, anR);        anS = fma2(hbS[2], w3, anS);
        lds2(w0, w1, a + 224);
        anR = fma2(hbR[3], w0, anR);        anS = fma2(hbS[3], w0, anS);
        anR = fma2(hbR[4], w1, anR);        anS = fma2(hbS[4], w1, anS);
        lds2(w2, w3, a + 240);
        anR = fma2(hbR[5], w2, anR);        anS = fma2(hbS[5], w2, anS);
        anR = fma2(hbR[6], w3, anR);        anS = fma2(hbS[6], w3, anS);
        lds2(w0, w1, a + 256);
        anR = fma2(hbR[7], w0, anR);        anS = fma2(hbS[7], w0, anS);  // w1 = Wm pair

        // Packed epilogue; hn pairs buffered and stored as 16B v2.u64 at odd jp.
        {
            u64 r2 = fma2(tanh2(mul2(arR, half2)), half2, half2);
            u64 z2 = fma2(tanh2(mul2(azR, half2)), half2, half2);
            u64 n2 = tanh2(fma2(r2, anR, winR));
            u64 hpr = mergelo(hbR[2 * jp], hbR[2 * jp + 1]);   // (h[2jp], h[2jp+1])
            u64 hn2 = fma2(z2, fma2(n2, neg12, hpr), n2);      // n + z*(h-n)
            if (jp & 1) { if (okR) stg2(ohR + (jp - 1) * 8, prevR, hn2); }
            else        prevR = hn2;
            outsR = fma2(hn2, w1, outsR);
        }
        {
            u64 r2 = fma2(tanh2(mul2(arS, half2)), half2, half2);
            u64 z2 = fma2(tanh2(mul2(azS, half2)), half2, half2);
            u64 n2 = tanh2(fma2(r2, anS, winS));
            u64 hps = mergelo(hbS[2 * jp], hbS[2 * jp + 1]);
            u64 hn2 = fma2(z2, fma2(n2, neg12, hps), n2);
            if (jp & 1) { if (okS) stg2(ohS + (jp - 1) * 8, prevS, hn2); }
            else        prevS = hn2;
            outsS = fma2(hn2, w1, outsS);
        }
    }

    float eR, oR, eS, oS;
    upk2(outsR, eR, oR);
    upk2(outsS, eS, oS);
    if (okR) out_o[rowR] = -__expf(eR + oR) * gR;
    if (okS) out_o[rowS] = -__expf(eS + oS) * gS;
}

extern "C" void kernel_launch(void* const* d_in, const int* in_sizes, int n_in,
                              void* d_out, int out_size) {
    const float* h    = (const float*)d_in[0];
    const float* g    = (const float*)d_in[1];
    const float* Wi_r = (const float*)d_in[2];
    const float* Wh_r = (const float*)d_in[3];
    const float* bh_r = (const float*)d_in[4];
    const float* Wi_z = (const float*)d_in[5];
    const float* Wh_z = (const float*)d_in[6];
    const float* bh_z = (const float*)d_in[7];
    const float* Wi_n = (const float*)d_in[8];
    const float* Wh_n = (const float*)d_in[9];
    const float* bh_n = (const float*)d_in[10];
    const float* Wm   = (const float*)d_in[11];
    const float* bm   = (const float*)d_in[12];

    int N = in_sizes[1];  // g has N elements
    float* out   = (float*)d_out;
    float* out_h = out;                       // [N, 8] row-major
    float* out_o = out + (size_t)N * HID;     // [N]

    int blocks = (N + ROWS_PER_BLOCK - 1) / ROWS_PER_BLOCK;  // 128 thr x 2 rows
    l2o_gru_kernel<<<blocks, TPB>>>(h, g,
                                    Wi_r, Wh_r, bh_r,
                                    Wi_z, Wh_z, bh_z,
                                    Wi_n, Wh_n, bh_n,
                                    Wm, bm,
                                    out_h, out_o, N);
}